// round 13
// baseline (speedup 1.0000x reference)
#include <cuda_runtime.h>
#include <cuda_bf16.h>
#include <math.h>
#include <stdint.h>

#define BB 2
#define NN 2048
#define CC 1024
#define HH 16
#define DD 64
#define MR (BB*NN)          // 4096 rows
#define QK_SCALE 0.125f     // 64^-0.5
#define LOG2E 1.4426950408889634f

// ---- global scratch (allocation-free rule) --------------------------------
__device__ float g_qkv[(size_t)MR * 3 * CC];                  // fp32 qkv
__device__ __nv_bfloat16 g_xh[(size_t)MR * CC],  g_xl[(size_t)MR * CC];
__device__ __nv_bfloat16 g_wqh[(size_t)3 * CC * CC], g_wql[(size_t)3 * CC * CC];
__device__ __nv_bfloat16 g_wph[(size_t)CC * CC], g_wpl[(size_t)CC * CC];
__device__ __nv_bfloat16 g_ah[(size_t)MR * CC],  g_al[(size_t)MR * CC];
// RoPE'd, split, head-contiguous [b][h][n][64]; Q pre-scaled by SCALE*log2e
__device__ __nv_bfloat16 g_Qh[(size_t)MR * CC], g_Ql[(size_t)MR * CC];
__device__ __nv_bfloat16 g_Kh[(size_t)MR * CC], g_Kl[(size_t)MR * CC];
__device__ __nv_bfloat16 g_Vh[(size_t)MR * CC], g_Vl[(size_t)MR * CC];

// ---- helpers --------------------------------------------------------------
__device__ __forceinline__ uint32_t smem_u32(const void* p) {
    return (uint32_t)__cvta_generic_to_shared(p);
}
__device__ __forceinline__ void cp16(uint32_t dst, const void* src) {
    asm volatile("cp.async.ca.shared.global [%0], [%1], 16;"
                 :: "r"(dst), "l"(src) : "memory");
}
__device__ __forceinline__ void cp_commit() {
    asm volatile("cp.async.commit_group;" ::: "memory");
}
__device__ __forceinline__ void cp_wait1() {
    asm volatile("cp.async.wait_group 1;" ::: "memory");
}
__device__ __forceinline__ void ldmx4(uint32_t* r, uint32_t addr) {
    asm volatile("ldmatrix.sync.aligned.m8n8.x4.shared.b16 {%0,%1,%2,%3}, [%4];"
                 : "=r"(r[0]), "=r"(r[1]), "=r"(r[2]), "=r"(r[3]) : "r"(addr));
}
__device__ __forceinline__ void ldmx4t(uint32_t* r, uint32_t addr) {
    asm volatile("ldmatrix.sync.aligned.m8n8.x4.trans.shared.b16 {%0,%1,%2,%3}, [%4];"
                 : "=r"(r[0]), "=r"(r[1]), "=r"(r[2]), "=r"(r[3]) : "r"(addr));
}
__device__ __forceinline__ void mma_bf16(float* c, const uint32_t* a, const uint32_t* b) {
    asm volatile(
        "mma.sync.aligned.m16n8k16.row.col.f32.bf16.bf16.f32 "
        "{%0,%1,%2,%3}, {%4,%5,%6,%7}, {%8,%9}, {%0,%1,%2,%3};"
        : "+f"(c[0]), "+f"(c[1]), "+f"(c[2]), "+f"(c[3])
        : "r"(a[0]), "r"(a[1]), "r"(a[2]), "r"(a[3]), "r"(b[0]), "r"(b[1]));
}
__device__ __forceinline__ uint32_t pack2bf(float x, float y) {
    __nv_bfloat162 h = __floats2bfloat162_rn(x, y);
    return *(uint32_t*)&h;
}
__device__ __forceinline__ void split2(float x, float y, uint32_t& hi, uint32_t& lo) {
    float hx = __bfloat162float(__float2bfloat16(x));
    float hy = __bfloat162float(__float2bfloat16(y));
    hi = pack2bf(hx, hy);
    lo = pack2bf(x - hx, y - hy);
}

// ---------------------------------------------------------------------------
// split fp32 -> hi/lo bf16 (vectorized by 4)
// ---------------------------------------------------------------------------
__global__ void split_kernel(const float* __restrict__ src,
                             __nv_bfloat16* __restrict__ hi,
                             __nv_bfloat16* __restrict__ lo, int n4) {
    int i = blockIdx.x * blockDim.x + threadIdx.x;
    if (i >= n4) return;
    float4 v = ((const float4*)src)[i];
    uint32_t h0, l0, h1, l1;
    split2(v.x, v.y, h0, l0);
    split2(v.z, v.w, h1, l1);
    ((uint2*)hi)[i] = make_uint2(h0, h1);
    ((uint2*)lo)[i] = make_uint2(l0, l1);
}

// ---------------------------------------------------------------------------
// prep: RoPE q/k, q scaled by QK_SCALE*log2e (exp2 softmax domain),
// split q/k/v into [b][h][n][64]
// ---------------------------------------------------------------------------
__global__ void prep_qkv(const float* __restrict__ qkv,
                         const float* __restrict__ freqs) {
    int gid = blockIdx.x * blockDim.x + threadIdx.x;
    int half = gid & 1;
    int h = (gid >> 1) & (HH - 1);
    int n = (gid >> 5) & (NN - 1);
    int b = gid >> 16;

    const float* base = qkv + (size_t)(b * NN + n) * 3 * CC + h * DD + half * 32;
    const float* fp = freqs + (size_t)n * 32 + half * 16;
    size_t orow = ((size_t)(b * HH + h) * NN + n) * 64 + half * 32;
    const float QS = QK_SCALE * LOG2E;

#pragma unroll
    for (int j = 0; j < 32; j += 4) {
        float c0, s0, c1, s1;
        __sincosf(fp[j / 2], &s0, &c0);
        __sincosf(fp[j / 2 + 1], &s1, &c1);
        uint32_t hi0, lo0, hi1, lo1;

        float4 q = *(const float4*)(base + j);
        split2((q.x * c0 - q.y * s0) * QS, (q.x * s0 + q.y * c0) * QS, hi0, lo0);
        split2((q.z * c1 - q.w * s1) * QS, (q.z * s1 + q.w * c1) * QS, hi1, lo1);
        *(uint2*)(g_Qh + orow + j) = make_uint2(hi0, hi1);
        *(uint2*)(g_Ql + orow + j) = make_uint2(lo0, lo1);

        float4 k = *(const float4*)(base + CC + j);
        split2(k.x * c0 - k.y * s0, k.x * s0 + k.y * c0, hi0, lo0);
        split2(k.z * c1 - k.w * s1, k.z * s1 + k.w * c1, hi1, lo1);
        *(uint2*)(g_Kh + orow + j) = make_uint2(hi0, hi1);
        *(uint2*)(g_Kl + orow + j) = make_uint2(lo0, lo1);

        float4 v = *(const float4*)(base + 2 * CC + j);
        split2(v.x, v.y, hi0, lo0);
        split2(v.z, v.w, hi1, lo1);
        *(uint2*)(g_Vh + orow + j) = make_uint2(hi0, hi1);
        *(uint2*)(g_Vl + orow + j) = make_uint2(lo0, lo1);
    }
}

// ---------------------------------------------------------------------------
// GEMM (round-7 proven config): CTA 128x128, K-chunk 32, 8 warps (64x32),
// cp.async(.ca) double-buffered, 2 CTAs/SM.
// ---------------------------------------------------------------------------
#define SPAD 40
#define G_ARR (128 * SPAD * 2)      // 10240 B per array
#define G_STAGE (4 * G_ARR)         // 40960 B per stage

__global__ __launch_bounds__(256, 2) void gemm_b16(
        const __nv_bfloat16* __restrict__ Ahg, const __nv_bfloat16* __restrict__ Alg,
        const __nv_bfloat16* __restrict__ Whg, const __nv_bfloat16* __restrict__ Wlg,
        const float* __restrict__ bias, float* __restrict__ Cm,
        int M, int Nc, int K) {
    extern __shared__ __align__(16) char sm[];
    const uint32_t sbase = smem_u32(sm);

    const int tid = threadIdx.x;
    const int wid = tid >> 5;
    const int lane = tid & 31;
    const int m0 = blockIdx.y * 128;
    const int n0 = blockIdx.x * 128;
    const int wm = (wid >> 2) * 64;
    const int wn = (wid & 3) * 32;

    const int lrow = tid >> 1;
    const int lcol = (tid & 1) * 16;
    const __nv_bfloat16* Ahp = Ahg + (size_t)(m0 + lrow) * K + lcol;
    const __nv_bfloat16* Alp = Alg + (size_t)(m0 + lrow) * K + lcol;
    const __nv_bfloat16* Whp = Whg + (size_t)(n0 + lrow) * K + lcol;
    const __nv_bfloat16* Wlp = Wlg + (size_t)(n0 + lrow) * K + lcol;
    const uint32_t ldst = sbase + (lrow * SPAD + lcol) * 2;

    float acc[4][4][4];
#pragma unroll
    for (int i = 0; i < 4; i++)
#pragma unroll
        for (int j = 0; j < 4; j++)
#pragma unroll
            for (int f = 0; f < 4; f++) acc[i][j][f] = 0.f;

    const uint32_t a_row = wm + (lane & 15);
    const uint32_t a_coff = (lane >> 4) * 8;
    const uint32_t b_row = wn + ((lane >> 4) << 3) + (lane & 7);
    const uint32_t b_coff = ((lane >> 3) & 1) * 8;

    {
        uint32_t d = ldst;
        cp16(d, Ahp); cp16(d + 16, Ahp + 8);
        cp16(d + G_ARR, Alp); cp16(d + G_ARR + 16, Alp + 8);
        cp16(d + 2 * G_ARR, Whp); cp16(d + 2 * G_ARR + 16, Whp + 8);
        cp16(d + 3 * G_ARR, Wlp); cp16(d + 3 * G_ARR + 16, Wlp + 8);
    }
    cp_commit();

    int buf = 0;
    for (int k0 = 0; k0 < K; k0 += 32) {
        if (k0 + 32 < K) {
            uint32_t d = ldst + (buf ^ 1) * G_STAGE;
            int kn = k0 + 32;
            cp16(d, Ahp + kn); cp16(d + 16, Ahp + kn + 8);
            cp16(d + G_ARR, Alp + kn); cp16(d + G_ARR + 16, Alp + kn + 8);
            cp16(d + 2 * G_ARR, Whp + kn); cp16(d + 2 * G_ARR + 16, Whp + kn + 8);
            cp16(d + 3 * G_ARR, Wlp + kn); cp16(d + 3 * G_ARR + 16, Wlp + kn + 8);
        }
        cp_commit();
        cp_wait1();
        __syncthreads();

        const uint32_t sAh = sbase + buf * G_STAGE;
        const uint32_t sAl = sAh + G_ARR;
        const uint32_t sBh = sAh + 2 * G_ARR;
        const uint32_t sBl = sAh + 3 * G_ARR;

#pragma unroll
        for (int ks = 0; ks < 2; ks++) {
            const uint32_t kc = ks * 16;
            uint32_t afh[4][4], afl[4][4];
#pragma unroll
            for (int mt = 0; mt < 4; mt++) {
                uint32_t off = ((a_row + mt * 16) * SPAD + kc + a_coff) * 2;
                ldmx4(afh[mt], sAh + off);
                ldmx4(afl[mt], sAl + off);
            }
            uint32_t bfh[2][4], bfl[2][4];
#pragma unroll
            for (int bt = 0; bt < 2; bt++) {
                uint32_t off = ((b_row + bt * 16) * SPAD + kc + b_coff) * 2;
                ldmx4(bfh[bt], sBh + off);
                ldmx4(bfl[bt], sBl + off);
            }
#pragma unroll
            for (int mt = 0; mt < 4; mt++)
#pragma unroll
                for (int nt = 0; nt < 4; nt++) {
                    uint32_t* bh = &bfh[nt >> 1][(nt & 1) * 2];
                    uint32_t* bl = &bfl[nt >> 1][(nt & 1) * 2];
                    mma_bf16(acc[mt][nt], afh[mt], bh);
                    mma_bf16(acc[mt][nt], afh[mt], bl);
                    mma_bf16(acc[mt][nt], afl[mt], bh);
                }
        }
        __syncthreads();
        buf ^= 1;
    }

    const int erow = lane >> 2;
    const int ecol = (lane & 3) * 2;
#pragma unroll
    for (int mt = 0; mt < 4; mt++) {
#pragma unroll
        for (int nt = 0; nt < 4; nt++) {
            int gr = m0 + wm + mt * 16 + erow;
            int gc = n0 + wn + nt * 8 + ecol;
            float b0 = 0.f, b1 = 0.f;
            if (bias) { b0 = bias[gc]; b1 = bias[gc + 1]; }
            *(float2*)(Cm + (size_t)gr * Nc + gc) =
                make_float2(acc[mt][nt][0] + b0, acc[mt][nt][1] + b1);
            *(float2*)(Cm + (size_t)(gr + 8) * Nc + gc) =
                make_float2(acc[mt][nt][2] + b0, acc[mt][nt][3] + b1);
        }
    }
}

// ---------------------------------------------------------------------------
// Flash attention, register-trimmed for 2 CTAs/SM (16 warps):
// - __launch_bounds__(256, 2) caps regs at 128
// - Q-low fragments reloaded from smem per iteration (Q smem stays resident)
// - P hi/lo packed inside the P.V ks-loop (short live range)
// 128 q-rows, 256 threads, 8 warps, cp.async(.ca) double-buffered K/V.
// ---------------------------------------------------------------------------
#define APAD 72
#define A_QARR (128 * APAD * 2)       // 18432 B (Qh or Ql)
#define A_KARR (64 * APAD * 2)        // 9216 B per KV array
#define A_KSTAGE (4 * A_KARR)         // 36864 B per stage
#define A_KBASE (2 * A_QARR)          // 36864  (total 110592 x2 = 221184 <= 228K)

__global__ __launch_bounds__(256, 2) void attn_mma(void) {
    extern __shared__ __align__(16) char sm[];
    const uint32_t sbase = smem_u32(sm);

    const int t = threadIdx.x;
    const int wid = t >> 5;
    const int lane = t & 31;
    const int h = blockIdx.y;
    const int b = blockIdx.z;
    const int q0 = blockIdx.x * 128;

    const size_t hbase = (size_t)(b * HH + h) * NN * 64;

    const int krow = t >> 2, kc16 = (t & 3) * 16;
    const uint32_t kdst = sbase + A_KBASE + (krow * APAD + kc16) * 2;
    const size_t ksrc0 = hbase + (size_t)krow * 64 + kc16;

    {
        uint32_t d = kdst;
        cp16(d, g_Kh + ksrc0); cp16(d + 16, g_Kh + ksrc0 + 8);
        cp16(d + A_KARR, g_Kl + ksrc0); cp16(d + A_KARR + 16, g_Kl + ksrc0 + 8);
        cp16(d + 2 * A_KARR, g_Vh + ksrc0); cp16(d + 2 * A_KARR + 16, g_Vh + ksrc0 + 8);
        cp16(d + 3 * A_KARR, g_Vl + ksrc0); cp16(d + 3 * A_KARR + 16, g_Vl + ksrc0 + 8);
    }
    cp_commit();

    __nv_bfloat16* const Qh = (__nv_bfloat16*)sm;
    __nv_bfloat16* const Ql = Qh + 128 * APAD;
    {
        int row = t >> 1, half = (t & 1) * 32;
        size_t src = hbase + (size_t)(q0 + row) * 64 + half;
        size_t dst = (size_t)row * APAD + half;
#pragma unroll
        for (int j = 0; j < 32; j += 8) {
            *(uint4*)(Qh + dst + j) = *(const uint4*)(g_Qh + src + j);
            *(uint4*)(Ql + dst + j) = *(const uint4*)(g_Ql + src + j);
        }
    }
    __syncthreads();

    // Q-hi fragments resident; Q-lo reloaded per iteration from smem.
    const uint32_t arow = wid * 16 + (lane & 15);
    const uint32_t acoff = (lane >> 4) * 8;
    uint32_t qfh[4][4];
#pragma unroll
    for (int ks = 0; ks < 4; ks++) {
        uint32_t off = (arow * APAD + ks * 16 + acoff) * 2;
        ldmx4(qfh[ks], sbase + off);
    }
    const uint32_t qloff = sbase + A_QARR + (arow * APAD + acoff) * 2;

    float o[8][4];
#pragma unroll
    for (int i = 0; i < 8; i++)
#pragma unroll
        for (int f = 0; f < 4; f++) o[i][f] = 0.f;
    float m0 = -1e30f, m1 = -1e30f, l0 = 0.f, l1 = 0.f;

    const uint32_t b_row = ((lane >> 4) << 3) + (lane & 7);
    const uint32_t b_coff = ((lane >> 3) & 1) * 8;
    const uint32_t v_row = ((lane >> 3) & 1) * 8 + (lane & 7);
    const uint32_t v_coff = (lane >> 4) * 8;

    int buf = 0;
    for (int kt = 0; kt < NN / 64; kt++) {
        if (kt + 1 < NN / 64) {
            uint32_t d = kdst + (buf ^ 1) * A_KSTAGE;
            size_t src = ksrc0 + (size_t)(kt + 1) * 64 * 64;
            cp16(d, g_Kh + src); cp16(d + 16, g_Kh + src + 8);
            cp16(d + A_KARR, g_Kl + src); cp16(d + A_KARR + 16, g_Kl + src + 8);
            cp16(d + 2 * A_KARR, g_Vh + src); cp16(d + 2 * A_KARR + 16, g_Vh + src + 8);
            cp16(d + 3 * A_KARR, g_Vl + src); cp16(d + 3 * A_KARR + 16, g_Vl + src + 8);
        }
        cp_commit();
        cp_wait1();
        __syncthreads();

        const uint32_t sKh = sbase + A_KBASE + buf * A_KSTAGE;
        const uint32_t sKl = sKh + A_KARR;
        const uint32_t sVh = sKh + 2 * A_KARR;
        const uint32_t sVl = sKh + 3 * A_KARR;

        // ---- S = Q.K^T (log2 domain) ----
        float s[8][4];
#pragma unroll
        for (int i = 0; i < 8; i++)
#pragma unroll
            for (int f = 0; f < 4; f++) s[i][f] = 0.f;
#pragma unroll
        for (int ks = 0; ks < 4; ks++) {
            const uint32_t kc = ks * 16;
            uint32_t qfl_t[4];
            ldmx4(qfl_t, qloff + kc * 2);
#pragma unroll
            for (int g = 0; g < 4; g++) {
                uint32_t bh[4], bl[4];
                uint32_t off = ((g * 16 + b_row) * APAD + kc + b_coff) * 2;
                ldmx4(bh, sKh + off);
                ldmx4(bl, sKl + off);
                mma_bf16(s[2 * g],     qfh[ks], &bh[0]);
                mma_bf16(s[2 * g],     qfh[ks], &bl[0]);
                mma_bf16(s[2 * g],     qfl_t,   &bh[0]);
                mma_bf16(s[2 * g + 1], qfh[ks], &bh[2]);
                mma_bf16(s[2 * g + 1], qfh[ks], &bl[2]);
                mma_bf16(s[2 * g + 1], qfl_t,   &bh[2]);
            }
        }

        // ---- online softmax (exp2 domain; l lane-partial) ----
        float tm0 = -1e30f, tm1 = -1e30f;
#pragma unroll
        for (int nt = 0; nt < 8; nt++) {
            tm0 = fmaxf(tm0, fmaxf(s[nt][0], s[nt][1]));
            tm1 = fmaxf(tm1, fmaxf(s[nt][2], s[nt][3]));
        }
        tm0 = fmaxf(tm0, __shfl_xor_sync(0xffffffffu, tm0, 1));
        tm0 = fmaxf(tm0, __shfl_xor_sync(0xffffffffu, tm0, 2));
        tm1 = fmaxf(tm1, __shfl_xor_sync(0xffffffffu, tm1, 1));
        tm1 = fmaxf(tm1, __shfl_xor_sync(0xffffffffu, tm1, 2));
        float mn0 = fmaxf(m0, tm0), mn1 = fmaxf(m1, tm1);
        float al0 = exp2f(m0 - mn0), al1 = exp2f(m1 - mn1);
        m0 = mn0; m1 = mn1;
        float rs0 = 0.f, rs1 = 0.f;
#pragma unroll
        for (int nt = 0; nt < 8; nt++) {
            s[nt][0] = exp2f(s[nt][0] - m0);
            s[nt][1] = exp2f(s[nt][1] - m0);
            s[nt][2] = exp2f(s[nt][2] - m1);
            s[nt][3] = exp2f(s[nt][3] - m1);
            rs0 += s[nt][0] + s[nt][1];
            rs1 += s[nt][2] + s[nt][3];
        }
        l0 = l0 * al0 + rs0;
        l1 = l1 * al1 + rs1;
#pragma unroll
        for (int nt = 0; nt < 8; nt++) {
            o[nt][0] *= al0; o[nt][1] *= al0;
            o[nt][2] *= al1; o[nt][3] *= al1;
        }

        // ---- O += P.V ; P packed per-ks (short live range) ----
#pragma unroll
        for (int ks = 0; ks < 4; ks++) {
            uint32_t ph[4], pl[4];
#pragma unroll
            for (int hf = 0; hf < 2; hf++) {
                int nt = 2 * ks + hf;
                split2(s[nt][0], s[nt][1], ph[hf * 2 + 0], pl[hf * 2 + 0]);
                split2(s[nt][2], s[nt][3], ph[hf * 2 + 1], pl[hf * 2 + 1]);
            }
            const uint32_t kr = ks * 16 + v_row;
#pragma unroll
            for (int g = 0; g < 4; g++) {
                uint32_t vh4[4], vl4[4];
                uint32_t off = (kr * APAD + g * 16 + v_coff) * 2;
                ldmx4t(vh4, sVh + off);
                ldmx4t(vl4, sVl + off);
                mma_bf16(o[2 * g],     ph, &vh4[0]);
                mma_bf16(o[2 * g],     ph, &vl4[0]);
                mma_bf16(o[2 * g],     pl, &vh4[0]);
                mma_bf16(o[2 * g + 1], ph, &vh4[2]);
                mma_bf16(o[2 * g + 1], ph, &vl4[2]);
                mma_bf16(o[2 * g + 1], pl, &vh4[2]);
            }
        }
        __syncthreads();
        buf ^= 1;
    }

    // ---- epilogue: reduce l, write pre-split ----
    l0 += __shfl_xor_sync(0xffffffffu, l0, 1);
    l0 += __shfl_xor_sync(0xffffffffu, l0, 2);
    l1 += __shfl_xor_sync(0xffffffffu, l1, 1);
    l1 += __shfl_xor_sync(0xffffffffu, l1, 2);
    float inv0 = 1.f / l0, inv1 = 1.f / l1;
    int r0 = q0 + wid * 16 + (lane >> 2);
    int cbase = (lane & 3) * 2;
    size_t base0 = (size_t)(b * NN + r0) * CC + h * DD + cbase;
    size_t base1 = base0 + (size_t)8 * CC;
#pragma unroll
    for (int nt = 0; nt < 8; nt++) {
        uint32_t hi, lo;
        split2(o[nt][0] * inv0, o[nt][1] * inv0, hi, lo);
        *(uint32_t*)(g_ah + base0 + nt * 8) = hi;
        *(uint32_t*)(g_al + base0 + nt * 8) = lo;
        split2(o[nt][2] * inv1, o[nt][3] * inv1, hi, lo);
        *(uint32_t*)(g_ah + base1 + nt * 8) = hi;
        *(uint32_t*)(g_al + base1 + nt * 8) = lo;
    }
}

// ---------------------------------------------------------------------------
extern "C" void kernel_launch(void* const* d_in, const int* in_sizes, int n_in,
                              void* d_out, int out_size) {
    const float* x      = (const float*)d_in[0];
    const float* freqs  = (const float*)d_in[1];
    const float* w_qkv  = (const float*)d_in[2];
    const float* w_proj = (const float*)d_in[3];
    const float* b_proj = (const float*)d_in[4];
    float* out = (float*)d_out;

    float* qkv;
    cudaGetSymbolAddress((void**)&qkv, g_qkv);
    __nv_bfloat16 *xh, *xl, *wqh, *wql, *wph, *wpl, *ah, *al;
    cudaGetSymbolAddress((void**)&xh, g_xh);
    cudaGetSymbolAddress((void**)&xl, g_xl);
    cudaGetSymbolAddress((void**)&wqh, g_wqh);
    cudaGetSymbolAddress((void**)&wql, g_wql);
    cudaGetSymbolAddress((void**)&wph, g_wph);
    cudaGetSymbolAddress((void**)&wpl, g_wpl);
    cudaGetSymbolAddress((void**)&ah, g_ah);
    cudaGetSymbolAddress((void**)&al, g_al);

    static int smem_set = 0;
    if (!smem_set) {
        cudaFuncSetAttribute(gemm_b16, cudaFuncAttributeMaxDynamicSharedMemorySize,
                             2 * G_STAGE);
        cudaFuncSetAttribute(attn_mma, cudaFuncAttributeMaxDynamicSharedMemorySize,
                             A_KBASE + 2 * A_KSTAGE);
        smem_set = 1;
    }

    // 0) pre-split inputs
    split_kernel<<<(MR * CC / 4 + 255) / 256, 256>>>(x, xh, xl, MR * CC / 4);
    split_kernel<<<(3 * CC * CC / 4 + 255) / 256, 256>>>(w_qkv, wqh, wql, 3 * CC * CC / 4);
    split_kernel<<<(CC * CC / 4 + 255) / 256, 256>>>(w_proj, wph, wpl, CC * CC / 4);

    // 1) qkv = x @ w_qkv^T
    gemm_b16<<<dim3(3 * CC / 128, MR / 128), 256, 2 * G_STAGE>>>(
        xh, xl, wqh, wql, nullptr, qkv, MR, 3 * CC, CC);
    // 2) RoPE + split q/k/v (head-contiguous; q pre-scaled for exp2 domain)
    prep_qkv<<<(BB * NN * HH * 2) / 256, 256>>>(qkv, freqs);
    // 3) attention (outputs pre-split g_ah/g_al)
    attn_mma<<<dim3(NN / 128, HH, BB), 256, A_KBASE + 2 * A_KSTAGE>>>();
    // 4) out = attn @ w_proj^T + b_proj
    gemm_b16<<<dim3(CC / 128, MR / 128), 256, 2 * G_STAGE>>>(
        ah, al, wph, wpl, b_proj, out, MR, CC, CC);
}

// round 14
// speedup vs baseline: 1.0152x; 1.0152x over previous
#include <cuda_runtime.h>
#include <cuda_bf16.h>
#include <math.h>
#include <stdint.h>

#define BB 2
#define NN 2048
#define CC 1024
#define HH 16
#define DD 64
#define MR (BB*NN)          // 4096 rows
#define QK_SCALE 0.125f     // 64^-0.5
#define LOG2E 1.4426950408889634f

// ---- global scratch (allocation-free rule) --------------------------------
__device__ float g_qkv[(size_t)MR * 3 * CC];                  // fp32 qkv
__device__ __nv_bfloat16 g_xh[(size_t)MR * CC],  g_xl[(size_t)MR * CC];
__device__ __nv_bfloat16 g_wqh[(size_t)3 * CC * CC], g_wql[(size_t)3 * CC * CC];
__device__ __nv_bfloat16 g_wph[(size_t)CC * CC], g_wpl[(size_t)CC * CC];
__device__ __nv_bfloat16 g_ah[(size_t)MR * CC],  g_al[(size_t)MR * CC];
// RoPE'd, split, head-contiguous [b][h][n][64]; Q pre-scaled by SCALE*log2e
__device__ __nv_bfloat16 g_Qh[(size_t)MR * CC], g_Ql[(size_t)MR * CC];
__device__ __nv_bfloat16 g_Kh[(size_t)MR * CC], g_Kl[(size_t)MR * CC];
__device__ __nv_bfloat16 g_Vh[(size_t)MR * CC], g_Vl[(size_t)MR * CC];

// ---- helpers --------------------------------------------------------------
__device__ __forceinline__ uint32_t smem_u32(const void* p) {
    return (uint32_t)__cvta_generic_to_shared(p);
}
__device__ __forceinline__ void cp16(uint32_t dst, const void* src) {
    asm volatile("cp.async.ca.shared.global [%0], [%1], 16;"
                 :: "r"(dst), "l"(src) : "memory");
}
__device__ __forceinline__ void cp_commit() {
    asm volatile("cp.async.commit_group;" ::: "memory");
}
__device__ __forceinline__ void cp_wait1() {
    asm volatile("cp.async.wait_group 1;" ::: "memory");
}
__device__ __forceinline__ void ldmx4(uint32_t* r, uint32_t addr) {
    asm volatile("ldmatrix.sync.aligned.m8n8.x4.shared.b16 {%0,%1,%2,%3}, [%4];"
                 : "=r"(r[0]), "=r"(r[1]), "=r"(r[2]), "=r"(r[3]) : "r"(addr));
}
__device__ __forceinline__ void ldmx4t(uint32_t* r, uint32_t addr) {
    asm volatile("ldmatrix.sync.aligned.m8n8.x4.trans.shared.b16 {%0,%1,%2,%3}, [%4];"
                 : "=r"(r[0]), "=r"(r[1]), "=r"(r[2]), "=r"(r[3]) : "r"(addr));
}
__device__ __forceinline__ void mma_bf16(float* c, const uint32_t* a, const uint32_t* b) {
    asm volatile(
        "mma.sync.aligned.m16n8k16.row.col.f32.bf16.bf16.f32 "
        "{%0,%1,%2,%3}, {%4,%5,%6,%7}, {%8,%9}, {%0,%1,%2,%3};"
        : "+f"(c[0]), "+f"(c[1]), "+f"(c[2]), "+f"(c[3])
        : "r"(a[0]), "r"(a[1]), "r"(a[2]), "r"(a[3]), "r"(b[0]), "r"(b[1]));
}
__device__ __forceinline__ uint32_t pack2bf(float x, float y) {
    __nv_bfloat162 h = __floats2bfloat162_rn(x, y);
    return *(uint32_t*)&h;
}
__device__ __forceinline__ void split2(float x, float y, uint32_t& hi, uint32_t& lo) {
    float hx = __bfloat162float(__float2bfloat16(x));
    float hy = __bfloat162float(__float2bfloat16(y));
    hi = pack2bf(hx, hy);
    lo = pack2bf(x - hx, y - hy);
}

// ---------------------------------------------------------------------------
// split fp32 -> hi/lo bf16 (vectorized by 4)
// ---------------------------------------------------------------------------
__global__ void split_kernel(const float* __restrict__ src,
                             __nv_bfloat16* __restrict__ hi,
                             __nv_bfloat16* __restrict__ lo, int n4) {
    int i = blockIdx.x * blockDim.x + threadIdx.x;
    if (i >= n4) return;
    float4 v = ((const float4*)src)[i];
    uint32_t h0, l0, h1, l1;
    split2(v.x, v.y, h0, l0);
    split2(v.z, v.w, h1, l1);
    ((uint2*)hi)[i] = make_uint2(h0, h1);
    ((uint2*)lo)[i] = make_uint2(l0, l1);
}

// ---------------------------------------------------------------------------
// prep: RoPE q/k, q scaled by QK_SCALE*log2e (exp2 softmax domain),
// split q/k/v into [b][h][n][64]
// ---------------------------------------------------------------------------
__global__ void prep_qkv(const float* __restrict__ qkv,
                         const float* __restrict__ freqs) {
    int gid = blockIdx.x * blockDim.x + threadIdx.x;
    int half = gid & 1;
    int h = (gid >> 1) & (HH - 1);
    int n = (gid >> 5) & (NN - 1);
    int b = gid >> 16;

    const float* base = qkv + (size_t)(b * NN + n) * 3 * CC + h * DD + half * 32;
    const float* fp = freqs + (size_t)n * 32 + half * 16;
    size_t orow = ((size_t)(b * HH + h) * NN + n) * 64 + half * 32;
    const float QS = QK_SCALE * LOG2E;

#pragma unroll
    for (int j = 0; j < 32; j += 4) {
        float c0, s0, c1, s1;
        __sincosf(fp[j / 2], &s0, &c0);
        __sincosf(fp[j / 2 + 1], &s1, &c1);
        uint32_t hi0, lo0, hi1, lo1;

        float4 q = *(const float4*)(base + j);
        split2((q.x * c0 - q.y * s0) * QS, (q.x * s0 + q.y * c0) * QS, hi0, lo0);
        split2((q.z * c1 - q.w * s1) * QS, (q.z * s1 + q.w * c1) * QS, hi1, lo1);
        *(uint2*)(g_Qh + orow + j) = make_uint2(hi0, hi1);
        *(uint2*)(g_Ql + orow + j) = make_uint2(lo0, lo1);

        float4 k = *(const float4*)(base + CC + j);
        split2(k.x * c0 - k.y * s0, k.x * s0 + k.y * c0, hi0, lo0);
        split2(k.z * c1 - k.w * s1, k.z * s1 + k.w * c1, hi1, lo1);
        *(uint2*)(g_Kh + orow + j) = make_uint2(hi0, hi1);
        *(uint2*)(g_Kl + orow + j) = make_uint2(lo0, lo1);

        float4 v = *(const float4*)(base + 2 * CC + j);
        split2(v.x, v.y, hi0, lo0);
        split2(v.z, v.w, hi1, lo1);
        *(uint2*)(g_Vh + orow + j) = make_uint2(hi0, hi1);
        *(uint2*)(g_Vl + orow + j) = make_uint2(lo0, lo1);
    }
}

// ---------------------------------------------------------------------------
// GEMM (round-7 proven config): CTA 128x128, K-chunk 32, 8 warps (64x32),
// cp.async(.ca) double-buffered, 2 CTAs/SM.
// ---------------------------------------------------------------------------
#define SPAD 40
#define G_ARR (128 * SPAD * 2)      // 10240 B per array
#define G_STAGE (4 * G_ARR)         // 40960 B per stage

__global__ __launch_bounds__(256, 2) void gemm_b16(
        const __nv_bfloat16* __restrict__ Ahg, const __nv_bfloat16* __restrict__ Alg,
        const __nv_bfloat16* __restrict__ Whg, const __nv_bfloat16* __restrict__ Wlg,
        const float* __restrict__ bias, float* __restrict__ Cm,
        int M, int Nc, int K) {
    extern __shared__ __align__(16) char sm[];
    const uint32_t sbase = smem_u32(sm);

    const int tid = threadIdx.x;
    const int wid = tid >> 5;
    const int lane = tid & 31;
    const int m0 = blockIdx.y * 128;
    const int n0 = blockIdx.x * 128;
    const int wm = (wid >> 2) * 64;
    const int wn = (wid & 3) * 32;

    const int lrow = tid >> 1;
    const int lcol = (tid & 1) * 16;
    const __nv_bfloat16* Ahp = Ahg + (size_t)(m0 + lrow) * K + lcol;
    const __nv_bfloat16* Alp = Alg + (size_t)(m0 + lrow) * K + lcol;
    const __nv_bfloat16* Whp = Whg + (size_t)(n0 + lrow) * K + lcol;
    const __nv_bfloat16* Wlp = Wlg + (size_t)(n0 + lrow) * K + lcol;
    const uint32_t ldst = sbase + (lrow * SPAD + lcol) * 2;

    float acc[4][4][4];
#pragma unroll
    for (int i = 0; i < 4; i++)
#pragma unroll
        for (int j = 0; j < 4; j++)
#pragma unroll
            for (int f = 0; f < 4; f++) acc[i][j][f] = 0.f;

    const uint32_t a_row = wm + (lane & 15);
    const uint32_t a_coff = (lane >> 4) * 8;
    const uint32_t b_row = wn + ((lane >> 4) << 3) + (lane & 7);
    const uint32_t b_coff = ((lane >> 3) & 1) * 8;

    {
        uint32_t d = ldst;
        cp16(d, Ahp); cp16(d + 16, Ahp + 8);
        cp16(d + G_ARR, Alp); cp16(d + G_ARR + 16, Alp + 8);
        cp16(d + 2 * G_ARR, Whp); cp16(d + 2 * G_ARR + 16, Whp + 8);
        cp16(d + 3 * G_ARR, Wlp); cp16(d + 3 * G_ARR + 16, Wlp + 8);
    }
    cp_commit();

    int buf = 0;
    for (int k0 = 0; k0 < K; k0 += 32) {
        if (k0 + 32 < K) {
            uint32_t d = ldst + (buf ^ 1) * G_STAGE;
            int kn = k0 + 32;
            cp16(d, Ahp + kn); cp16(d + 16, Ahp + kn + 8);
            cp16(d + G_ARR, Alp + kn); cp16(d + G_ARR + 16, Alp + kn + 8);
            cp16(d + 2 * G_ARR, Whp + kn); cp16(d + 2 * G_ARR + 16, Whp + kn + 8);
            cp16(d + 3 * G_ARR, Wlp + kn); cp16(d + 3 * G_ARR + 16, Wlp + kn + 8);
        }
        cp_commit();
        cp_wait1();
        __syncthreads();

        const uint32_t sAh = sbase + buf * G_STAGE;
        const uint32_t sAl = sAh + G_ARR;
        const uint32_t sBh = sAh + 2 * G_ARR;
        const uint32_t sBl = sAh + 3 * G_ARR;

#pragma unroll
        for (int ks = 0; ks < 2; ks++) {
            const uint32_t kc = ks * 16;
            uint32_t afh[4][4], afl[4][4];
#pragma unroll
            for (int mt = 0; mt < 4; mt++) {
                uint32_t off = ((a_row + mt * 16) * SPAD + kc + a_coff) * 2;
                ldmx4(afh[mt], sAh + off);
                ldmx4(afl[mt], sAl + off);
            }
            uint32_t bfh[2][4], bfl[2][4];
#pragma unroll
            for (int bt = 0; bt < 2; bt++) {
                uint32_t off = ((b_row + bt * 16) * SPAD + kc + b_coff) * 2;
                ldmx4(bfh[bt], sBh + off);
                ldmx4(bfl[bt], sBl + off);
            }
#pragma unroll
            for (int mt = 0; mt < 4; mt++)
#pragma unroll
                for (int nt = 0; nt < 4; nt++) {
                    uint32_t* bh = &bfh[nt >> 1][(nt & 1) * 2];
                    uint32_t* bl = &bfl[nt >> 1][(nt & 1) * 2];
                    mma_bf16(acc[mt][nt], afh[mt], bh);
                    mma_bf16(acc[mt][nt], afh[mt], bl);
                    mma_bf16(acc[mt][nt], afl[mt], bh);
                }
        }
        __syncthreads();
        buf ^= 1;
    }

    const int erow = lane >> 2;
    const int ecol = (lane & 3) * 2;
#pragma unroll
    for (int mt = 0; mt < 4; mt++) {
#pragma unroll
        for (int nt = 0; nt < 4; nt++) {
            int gr = m0 + wm + mt * 16 + erow;
            int gc = n0 + wn + nt * 8 + ecol;
            float b0 = 0.f, b1 = 0.f;
            if (bias) { b0 = bias[gc]; b1 = bias[gc + 1]; }
            *(float2*)(Cm + (size_t)gr * Nc + gc) =
                make_float2(acc[mt][nt][0] + b0, acc[mt][nt][1] + b1);
            *(float2*)(Cm + (size_t)(gr + 8) * Nc + gc) =
                make_float2(acc[mt][nt][2] + b0, acc[mt][nt][3] + b1);
        }
    }
}

// ---------------------------------------------------------------------------
// Flash attention (round-12 best config): 128 q-rows, 256 threads, 8 warps,
// cp.async(.ca) double-buffered K/V, exp2-domain softmax, deferred l-reduce.
// ---------------------------------------------------------------------------
#define APAD 72
#define A_QARR (128 * APAD * 2)       // 18432 B (Qh or Ql)
#define A_KARR (64 * APAD * 2)        // 9216 B per KV array
#define A_KSTAGE (4 * A_KARR)         // 36864 B per stage
#define A_KBASE (2 * A_QARR)          // 36864

__global__ __launch_bounds__(256, 1) void attn_mma(void) {
    extern __shared__ __align__(16) char sm[];
    const uint32_t sbase = smem_u32(sm);

    const int t = threadIdx.x;
    const int wid = t >> 5;
    const int lane = t & 31;
    const int h = blockIdx.y;
    const int b = blockIdx.z;
    const int q0 = blockIdx.x * 128;

    const size_t hbase = (size_t)(b * HH + h) * NN * 64;

    const int krow = t >> 2, kc16 = (t & 3) * 16;
    const uint32_t kdst = sbase + A_KBASE + (krow * APAD + kc16) * 2;
    const size_t ksrc0 = hbase + (size_t)krow * 64 + kc16;

    {
        uint32_t d = kdst;
        cp16(d, g_Kh + ksrc0); cp16(d + 16, g_Kh + ksrc0 + 8);
        cp16(d + A_KARR, g_Kl + ksrc0); cp16(d + A_KARR + 16, g_Kl + ksrc0 + 8);
        cp16(d + 2 * A_KARR, g_Vh + ksrc0); cp16(d + 2 * A_KARR + 16, g_Vh + ksrc0 + 8);
        cp16(d + 3 * A_KARR, g_Vl + ksrc0); cp16(d + 3 * A_KARR + 16, g_Vl + ksrc0 + 8);
    }
    cp_commit();

    __nv_bfloat16* const Qh = (__nv_bfloat16*)sm;
    __nv_bfloat16* const Ql = Qh + 128 * APAD;
    {
        int row = t >> 1, half = (t & 1) * 32;
        size_t src = hbase + (size_t)(q0 + row) * 64 + half;
        size_t dst = (size_t)row * APAD + half;
#pragma unroll
        for (int j = 0; j < 32; j += 8) {
            *(uint4*)(Qh + dst + j) = *(const uint4*)(g_Qh + src + j);
            *(uint4*)(Ql + dst + j) = *(const uint4*)(g_Ql + src + j);
        }
    }
    __syncthreads();

    uint32_t qfh[4][4], qfl[4][4];
    {
        const uint32_t arow = wid * 16 + (lane & 15);
        const uint32_t acoff = (lane >> 4) * 8;
#pragma unroll
        for (int ks = 0; ks < 4; ks++) {
            uint32_t off = (arow * APAD + ks * 16 + acoff) * 2;
            ldmx4(qfh[ks], sbase + off);
            ldmx4(qfl[ks], sbase + A_QARR + off);
        }
    }

    float o[8][4];
#pragma unroll
    for (int i = 0; i < 8; i++)
#pragma unroll
        for (int f = 0; f < 4; f++) o[i][f] = 0.f;
    float m0 = -1e30f, m1 = -1e30f, l0 = 0.f, l1 = 0.f;   // l lane-partial

    const uint32_t b_row = ((lane >> 4) << 3) + (lane & 7);
    const uint32_t b_coff = ((lane >> 3) & 1) * 8;
    const uint32_t v_row = ((lane >> 3) & 1) * 8 + (lane & 7);
    const uint32_t v_coff = (lane >> 4) * 8;

    int buf = 0;
    for (int kt = 0; kt < NN / 64; kt++) {
        if (kt + 1 < NN / 64) {
            uint32_t d = kdst + (buf ^ 1) * A_KSTAGE;
            size_t src = ksrc0 + (size_t)(kt + 1) * 64 * 64;
            cp16(d, g_Kh + src); cp16(d + 16, g_Kh + src + 8);
            cp16(d + A_KARR, g_Kl + src); cp16(d + A_KARR + 16, g_Kl + src + 8);
            cp16(d + 2 * A_KARR, g_Vh + src); cp16(d + 2 * A_KARR + 16, g_Vh + src + 8);
            cp16(d + 3 * A_KARR, g_Vl + src); cp16(d + 3 * A_KARR + 16, g_Vl + src + 8);
        }
        cp_commit();
        cp_wait1();
        __syncthreads();

        const uint32_t sKh = sbase + A_KBASE + buf * A_KSTAGE;
        const uint32_t sKl = sKh + A_KARR;
        const uint32_t sVh = sKh + 2 * A_KARR;
        const uint32_t sVl = sKh + 3 * A_KARR;

        // ---- S = Q.K^T (log2 domain) ----
        float s[8][4];
#pragma unroll
        for (int i = 0; i < 8; i++)
#pragma unroll
            for (int f = 0; f < 4; f++) s[i][f] = 0.f;
#pragma unroll
        for (int ks = 0; ks < 4; ks++) {
            const uint32_t kc = ks * 16;
#pragma unroll
            for (int g = 0; g < 4; g++) {
                uint32_t bh[4], bl[4];
                uint32_t off = ((g * 16 + b_row) * APAD + kc + b_coff) * 2;
                ldmx4(bh, sKh + off);
                ldmx4(bl, sKl + off);
                mma_bf16(s[2 * g],     qfh[ks], &bh[0]);
                mma_bf16(s[2 * g],     qfh[ks], &bl[0]);
                mma_bf16(s[2 * g],     qfl[ks], &bh[0]);
                mma_bf16(s[2 * g + 1], qfh[ks], &bh[2]);
                mma_bf16(s[2 * g + 1], qfh[ks], &bl[2]);
                mma_bf16(s[2 * g + 1], qfl[ks], &bh[2]);
            }
        }

        // ---- online softmax (exp2 domain; l lane-partial) ----
        float tm0 = -1e30f, tm1 = -1e30f;
#pragma unroll
        for (int nt = 0; nt < 8; nt++) {
            tm0 = fmaxf(tm0, fmaxf(s[nt][0], s[nt][1]));
            tm1 = fmaxf(tm1, fmaxf(s[nt][2], s[nt][3]));
        }
        tm0 = fmaxf(tm0, __shfl_xor_sync(0xffffffffu, tm0, 1));
        tm0 = fmaxf(tm0, __shfl_xor_sync(0xffffffffu, tm0, 2));
        tm1 = fmaxf(tm1, __shfl_xor_sync(0xffffffffu, tm1, 1));
        tm1 = fmaxf(tm1, __shfl_xor_sync(0xffffffffu, tm1, 2));
        float mn0 = fmaxf(m0, tm0), mn1 = fmaxf(m1, tm1);
        float al0 = exp2f(m0 - mn0), al1 = exp2f(m1 - mn1);
        m0 = mn0; m1 = mn1;
        float rs0 = 0.f, rs1 = 0.f;
#pragma unroll
        for (int nt = 0; nt < 8; nt++) {
            s[nt][0] = exp2f(s[nt][0] - m0);
            s[nt][1] = exp2f(s[nt][1] - m0);
            s[nt][2] = exp2f(s[nt][2] - m1);
            s[nt][3] = exp2f(s[nt][3] - m1);
            rs0 += s[nt][0] + s[nt][1];
            rs1 += s[nt][2] + s[nt][3];
        }
        l0 = l0 * al0 + rs0;
        l1 = l1 * al1 + rs1;
#pragma unroll
        for (int nt = 0; nt < 8; nt++) {
            o[nt][0] *= al0; o[nt][1] *= al0;
            o[nt][2] *= al1; o[nt][3] *= al1;
        }

        // ---- pack P hi/lo from registers ----
        uint32_t ph[4][4], pl[4][4];
#pragma unroll
        for (int ks = 0; ks < 4; ks++) {
#pragma unroll
            for (int hf = 0; hf < 2; hf++) {
                int nt = 2 * ks + hf;
                split2(s[nt][0], s[nt][1], ph[ks][hf * 2 + 0], pl[ks][hf * 2 + 0]);
                split2(s[nt][2], s[nt][3], ph[ks][hf * 2 + 1], pl[ks][hf * 2 + 1]);
            }
        }

        // ---- O += P.V ----
#pragma unroll
        for (int ks = 0; ks < 4; ks++) {
            const uint32_t kr = ks * 16 + v_row;
#pragma unroll
            for (int g = 0; g < 4; g++) {
                uint32_t vh4[4], vl4[4];
                uint32_t off = (kr * APAD + g * 16 + v_coff) * 2;
                ldmx4t(vh4, sVh + off);
                ldmx4t(vl4, sVl + off);
                mma_bf16(o[2 * g],     ph[ks], &vh4[0]);
                mma_bf16(o[2 * g],     ph[ks], &vl4[0]);
                mma_bf16(o[2 * g],     pl[ks], &vh4[0]);
                mma_bf16(o[2 * g + 1], ph[ks], &vh4[2]);
                mma_bf16(o[2 * g + 1], ph[ks], &vl4[2]);
                mma_bf16(o[2 * g + 1], pl[ks], &vh4[2]);
            }
        }
        __syncthreads();
        buf ^= 1;
    }

    // ---- epilogue: reduce l, write pre-split ----
    l0 += __shfl_xor_sync(0xffffffffu, l0, 1);
    l0 += __shfl_xor_sync(0xffffffffu, l0, 2);
    l1 += __shfl_xor_sync(0xffffffffu, l1, 1);
    l1 += __shfl_xor_sync(0xffffffffu, l1, 2);
    float inv0 = 1.f / l0, inv1 = 1.f / l1;
    int r0 = q0 + wid * 16 + (lane >> 2);
    int cbase = (lane & 3) * 2;
    size_t base0 = (size_t)(b * NN + r0) * CC + h * DD + cbase;
    size_t base1 = base0 + (size_t)8 * CC;
#pragma unroll
    for (int nt = 0; nt < 8; nt++) {
        uint32_t hi, lo;
        split2(o[nt][0] * inv0, o[nt][1] * inv0, hi, lo);
        *(uint32_t*)(g_ah + base0 + nt * 8) = hi;
        *(uint32_t*)(g_al + base0 + nt * 8) = lo;
        split2(o[nt][2] * inv1, o[nt][3] * inv1, hi, lo);
        *(uint32_t*)(g_ah + base1 + nt * 8) = hi;
        *(uint32_t*)(g_al + base1 + nt * 8) = lo;
    }
}

// ---------------------------------------------------------------------------
extern "C" void kernel_launch(void* const* d_in, const int* in_sizes, int n_in,
                              void* d_out, int out_size) {
    const float* x      = (const float*)d_in[0];
    const float* freqs  = (const float*)d_in[1];
    const float* w_qkv  = (const float*)d_in[2];
    const float* w_proj = (const float*)d_in[3];
    const float* b_proj = (const float*)d_in[4];
    float* out = (float*)d_out;

    float* qkv;
    cudaGetSymbolAddress((void**)&qkv, g_qkv);
    __nv_bfloat16 *xh, *xl, *wqh, *wql, *wph, *wpl, *ah, *al;
    cudaGetSymbolAddress((void**)&xh, g_xh);
    cudaGetSymbolAddress((void**)&xl, g_xl);
    cudaGetSymbolAddress((void**)&wqh, g_wqh);
    cudaGetSymbolAddress((void**)&wql, g_wql);
    cudaGetSymbolAddress((void**)&wph, g_wph);
    cudaGetSymbolAddress((void**)&wpl, g_wpl);
    cudaGetSymbolAddress((void**)&ah, g_ah);
    cudaGetSymbolAddress((void**)&al, g_al);

    static int init_done = 0;
    static cudaStream_t sA, sB;
    static cudaEvent_t evRoot, evA, evB;
    if (!init_done) {
        cudaFuncSetAttribute(gemm_b16, cudaFuncAttributeMaxDynamicSharedMemorySize,
                             2 * G_STAGE);
        cudaFuncSetAttribute(attn_mma, cudaFuncAttributeMaxDynamicSharedMemorySize,
                             A_KBASE + 2 * A_KSTAGE);
        cudaStreamCreateWithFlags(&sA, cudaStreamNonBlocking);
        cudaStreamCreateWithFlags(&sB, cudaStreamNonBlocking);
        cudaEventCreateWithFlags(&evRoot, cudaEventDisableTiming);
        cudaEventCreateWithFlags(&evA, cudaEventDisableTiming);
        cudaEventCreateWithFlags(&evB, cudaEventDisableTiming);
        init_done = 1;
    }

    // ---- fork: run the three independent splits concurrently ----
    cudaEventRecord(evRoot, 0);
    cudaStreamWaitEvent(sA, evRoot, 0);
    cudaStreamWaitEvent(sB, evRoot, 0);

    // main stream: split x (needed by gemm1)
    split_kernel<<<(MR * CC / 4 + 255) / 256, 256>>>(x, xh, xl, MR * CC / 4);
    // stream A: split w_qkv (needed by gemm1)
    split_kernel<<<(3 * CC * CC / 4 + 255) / 256, 256, 0, sA>>>(
        w_qkv, wqh, wql, 3 * CC * CC / 4);
    // stream B: split w_proj (needed only by gemm2 — hidden behind gemm1+attn)
    split_kernel<<<(CC * CC / 4 + 255) / 256, 256, 0, sB>>>(
        w_proj, wph, wpl, CC * CC / 4);

    cudaEventRecord(evA, sA);
    cudaEventRecord(evB, sB);

    // join w_qkv split before gemm1
    cudaStreamWaitEvent(0, evA, 0);

    // 1) qkv = x @ w_qkv^T
    gemm_b16<<<dim3(3 * CC / 128, MR / 128), 256, 2 * G_STAGE>>>(
        xh, xl, wqh, wql, nullptr, qkv, MR, 3 * CC, CC);
    // 2) RoPE + split q/k/v (head-contiguous; q pre-scaled for exp2 domain)
    prep_qkv<<<(BB * NN * HH * 2) / 256, 256>>>(qkv, freqs);
    // 3) attention (outputs pre-split g_ah/g_al)
    attn_mma<<<dim3(NN / 128, HH, BB), 256, A_KBASE + 2 * A_KSTAGE>>>();

    // join w_proj split before gemm2
    cudaStreamWaitEvent(0, evB, 0);

    // 4) out = attn @ w_proj^T + b_proj
    gemm_b16<<<dim3(CC / 128, MR / 128), 256, 2 * G_STAGE>>>(
        ah, al, wph, wpl, b_proj, out, MR, CC, CC);
}

// round 15
// speedup vs baseline: 1.1026x; 1.0862x over previous
#include <cuda_runtime.h>
#include <cuda_bf16.h>
#include <math.h>
#include <stdint.h>

#define BB 2
#define NN 2048
#define CC 1024
#define HH 16
#define DD 64
#define MR (BB*NN)          // 4096 rows
#define QK_SCALE 0.125f     // 64^-0.5
#define LOG2E 1.4426950408889634f

// ---- global scratch (allocation-free rule) --------------------------------
__device__ float g_qkv[(size_t)MR * 3 * CC];    // fp32 qkv (gemm1 out)
__device__ float g_attn[(size_t)MR * CC];       // fp32 attn out (gemm2 in)
// RoPE'd, split, head-contiguous [b][h][n][64]; Q pre-scaled by SCALE*log2e
__device__ __nv_bfloat16 g_Qh[(size_t)MR * CC], g_Ql[(size_t)MR * CC];
__device__ __nv_bfloat16 g_Kh[(size_t)MR * CC], g_Kl[(size_t)MR * CC];
__device__ __nv_bfloat16 g_Vh[(size_t)MR * CC], g_Vl[(size_t)MR * CC];

// ---- helpers --------------------------------------------------------------
__device__ __forceinline__ uint32_t smem_u32(const void* p) {
    return (uint32_t)__cvta_generic_to_shared(p);
}
__device__ __forceinline__ void cp16(uint32_t dst, const void* src) {
    asm volatile("cp.async.ca.shared.global [%0], [%1], 16;"
                 :: "r"(dst), "l"(src) : "memory");
}
__device__ __forceinline__ void cp_commit() {
    asm volatile("cp.async.commit_group;" ::: "memory");
}
__device__ __forceinline__ void cp_wait1() {
    asm volatile("cp.async.wait_group 1;" ::: "memory");
}
__device__ __forceinline__ void ldmx4(uint32_t* r, uint32_t addr) {
    asm volatile("ldmatrix.sync.aligned.m8n8.x4.shared.b16 {%0,%1,%2,%3}, [%4];"
                 : "=r"(r[0]), "=r"(r[1]), "=r"(r[2]), "=r"(r[3]) : "r"(addr));
}
__device__ __forceinline__ void ldmx4t(uint32_t* r, uint32_t addr) {
    asm volatile("ldmatrix.sync.aligned.m8n8.x4.trans.shared.b16 {%0,%1,%2,%3}, [%4];"
                 : "=r"(r[0]), "=r"(r[1]), "=r"(r[2]), "=r"(r[3]) : "r"(addr));
}
__device__ __forceinline__ void mma_bf16(float* c, const uint32_t* a, const uint32_t* b) {
    asm volatile(
        "mma.sync.aligned.m16n8k16.row.col.f32.bf16.bf16.f32 "
        "{%0,%1,%2,%3}, {%4,%5,%6,%7}, {%8,%9}, {%0,%1,%2,%3};"
        : "+f"(c[0]), "+f"(c[1]), "+f"(c[2]), "+f"(c[3])
        : "r"(a[0]), "r"(a[1]), "r"(a[2]), "r"(a[3]), "r"(b[0]), "r"(b[1]));
}
__device__ __forceinline__ void mma_tf32(float* c, const uint32_t* a, const uint32_t* b) {
    asm volatile(
        "mma.sync.aligned.m16n8k8.row.col.f32.tf32.tf32.f32 "
        "{%0,%1,%2,%3}, {%4,%5,%6,%7}, {%8,%9}, {%0,%1,%2,%3};"
        : "+f"(c[0]), "+f"(c[1]), "+f"(c[2]), "+f"(c[3])
        : "r"(a[0]), "r"(a[1]), "r"(a[2]), "r"(a[3]), "r"(b[0]), "r"(b[1]));
}
__device__ __forceinline__ void cvt_tf32x4(uint32_t* r) {
#pragma unroll
    for (int i = 0; i < 4; i++) {
        float f = __uint_as_float(r[i]);
        asm volatile("cvt.rna.tf32.f32 %0, %1;" : "=r"(r[i]) : "f"(f));
    }
}
__device__ __forceinline__ uint32_t pack2bf(float x, float y) {
    __nv_bfloat162 h = __floats2bfloat162_rn(x, y);
    return *(uint32_t*)&h;
}
__device__ __forceinline__ void split2(float x, float y, uint32_t& hi, uint32_t& lo) {
    float hx = __bfloat162float(__float2bfloat16(x));
    float hy = __bfloat162float(__float2bfloat16(y));
    hi = pack2bf(hx, hy);
    lo = pack2bf(x - hx, y - hy);
}

// ---------------------------------------------------------------------------
// prep: RoPE q/k, q scaled by QK_SCALE*log2e, split q/k/v into [b][h][n][64]
// ---------------------------------------------------------------------------
__global__ void prep_qkv(const float* __restrict__ qkv,
                         const float* __restrict__ freqs) {
    int gid = blockIdx.x * blockDim.x + threadIdx.x;
    int half = gid & 1;
    int h = (gid >> 1) & (HH - 1);
    int n = (gid >> 5) & (NN - 1);
    int b = gid >> 16;

    const float* base = qkv + (size_t)(b * NN + n) * 3 * CC + h * DD + half * 32;
    const float* fp = freqs + (size_t)n * 32 + half * 16;
    size_t orow = ((size_t)(b * HH + h) * NN + n) * 64 + half * 32;
    const float QS = QK_SCALE * LOG2E;

#pragma unroll
    for (int j = 0; j < 32; j += 4) {
        float c0, s0, c1, s1;
        __sincosf(fp[j / 2], &s0, &c0);
        __sincosf(fp[j / 2 + 1], &s1, &c1);
        uint32_t hi0, lo0, hi1, lo1;

        float4 q = *(const float4*)(base + j);
        split2((q.x * c0 - q.y * s0) * QS, (q.x * s0 + q.y * c0) * QS, hi0, lo0);
        split2((q.z * c1 - q.w * s1) * QS, (q.z * s1 + q.w * c1) * QS, hi1, lo1);
        *(uint2*)(g_Qh + orow + j) = make_uint2(hi0, hi1);
        *(uint2*)(g_Ql + orow + j) = make_uint2(lo0, lo1);

        float4 k = *(const float4*)(base + CC + j);
        split2(k.x * c0 - k.y * s0, k.x * s0 + k.y * c0, hi0, lo0);
        split2(k.z * c1 - k.w * s1, k.z * s1 + k.w * c1, hi1, lo1);
        *(uint2*)(g_Kh + orow + j) = make_uint2(hi0, hi1);
        *(uint2*)(g_Kl + orow + j) = make_uint2(lo0, lo1);

        float4 v = *(const float4*)(base + 2 * CC + j);
        split2(v.x, v.y, hi0, lo0);
        split2(v.z, v.w, hi1, lo1);
        *(uint2*)(g_Vh + orow + j) = make_uint2(hi0, hi1);
        *(uint2*)(g_Vl + orow + j) = make_uint2(lo0, lo1);
    }
}

// ---------------------------------------------------------------------------
// tf32 GEMM: Cm[M,Nc] = A[M,K] @ W[Nc,K]^T (+bias), fp32 I/O, single-pass.
// CTA 128x128, K-chunk 32 (4 x k8 MMA steps), 8 warps (64x32 warp tile),
// cp.async double-buffered raw fp32 staging, cvt.rna in-register, 2 CTAs/SM.
// ---------------------------------------------------------------------------
#define SPADF 36                      // floats per smem row (32 data + 4 pad)
#define GF_ARR (128 * SPADF * 4)      // 18432 B per array
#define GF_STAGE (2 * GF_ARR)         // 36864 B per stage

__global__ __launch_bounds__(256, 2) void gemm_tf32(
        const float* __restrict__ A, const float* __restrict__ W,
        const float* __restrict__ bias, float* __restrict__ Cm,
        int M, int Nc, int K) {
    extern __shared__ __align__(16) char sm[];
    const uint32_t sbase = smem_u32(sm);

    const int tid = threadIdx.x;
    const int wid = tid >> 5;
    const int lane = tid & 31;
    const int m0 = blockIdx.y * 128;
    const int n0 = blockIdx.x * 128;
    const int wm = (wid >> 2) * 64;
    const int wn = (wid & 3) * 32;

    const int lrow = tid >> 1;
    const int lcolf = (tid & 1) * 16;          // 16 floats per thread
    const float* Ap = A + (size_t)(m0 + lrow) * K + lcolf;
    const float* Wp = W + (size_t)(n0 + lrow) * K + lcolf;
    const uint32_t adst = sbase + (lrow * SPADF + lcolf) * 4;
    const uint32_t bdst = adst + GF_ARR;

    float acc[4][4][4];
#pragma unroll
    for (int i = 0; i < 4; i++)
#pragma unroll
        for (int j = 0; j < 4; j++)
#pragma unroll
            for (int f = 0; f < 4; f++) acc[i][j][f] = 0.f;

    // fragment addressing (fp32 columns)
    const uint32_t a_row = wm + (lane & 15);
    const uint32_t a_coff = (lane >> 4) * 4;
    const uint32_t b_row = wn + ((lane >> 4) << 3) + (lane & 7);
    const uint32_t b_coff = ((lane >> 3) & 1) * 4;

    // prefetch stage 0
#pragma unroll
    for (int c = 0; c < 4; c++) {
        cp16(adst + c * 16, Ap + c * 4);
        cp16(bdst + c * 16, Wp + c * 4);
    }
    cp_commit();

    int buf = 0;
    for (int k0 = 0; k0 < K; k0 += 32) {
        if (k0 + 32 < K) {
            uint32_t d = (buf ^ 1) * GF_STAGE;
            int kn = k0 + 32;
#pragma unroll
            for (int c = 0; c < 4; c++) {
                cp16(adst + d + c * 16, Ap + kn + c * 4);
                cp16(bdst + d + c * 16, Wp + kn + c * 4);
            }
        }
        cp_commit();
        cp_wait1();
        __syncthreads();

        const uint32_t sA = sbase + buf * GF_STAGE;
        const uint32_t sB = sA + GF_ARR;

#pragma unroll
        for (int ks = 0; ks < 4; ks++) {
            const uint32_t kc = ks * 8;
            uint32_t af[4][4];
#pragma unroll
            for (int mt = 0; mt < 4; mt++) {
                ldmx4(af[mt], sA + ((a_row + mt * 16) * SPADF + kc + a_coff) * 4);
                cvt_tf32x4(af[mt]);
            }
            uint32_t bf[2][4];
#pragma unroll
            for (int p = 0; p < 2; p++) {
                ldmx4(bf[p], sB + ((b_row + p * 16) * SPADF + kc + b_coff) * 4);
                cvt_tf32x4(bf[p]);
            }
#pragma unroll
            for (int mt = 0; mt < 4; mt++)
#pragma unroll
                for (int p = 0; p < 2; p++) {
                    mma_tf32(acc[mt][2 * p],     af[mt], &bf[p][0]);
                    mma_tf32(acc[mt][2 * p + 1], af[mt], &bf[p][2]);
                }
        }
        __syncthreads();
        buf ^= 1;
    }

    const int erow = lane >> 2;
    const int ecol = (lane & 3) * 2;
#pragma unroll
    for (int mt = 0; mt < 4; mt++) {
#pragma unroll
        for (int nt = 0; nt < 4; nt++) {
            int gr = m0 + wm + mt * 16 + erow;
            int gc = n0 + wn + nt * 8 + ecol;
            float b0 = 0.f, b1 = 0.f;
            if (bias) { b0 = bias[gc]; b1 = bias[gc + 1]; }
            *(float2*)(Cm + (size_t)gr * Nc + gc) =
                make_float2(acc[mt][nt][0] + b0, acc[mt][nt][1] + b1);
            *(float2*)(Cm + (size_t)(gr + 8) * Nc + gc) =
                make_float2(acc[mt][nt][2] + b0, acc[mt][nt][3] + b1);
        }
    }
}

// ---------------------------------------------------------------------------
// Flash attention (round-12 best config): 128 q-rows, 256 threads, 8 warps,
// cp.async double-buffered K/V, bf16 3-term split, exp2 softmax.
// Epilogue writes plain fp32 g_attn (gemm2 converts on load).
// ---------------------------------------------------------------------------
#define APAD 72
#define A_QARR (128 * APAD * 2)       // 18432 B (Qh or Ql)
#define A_KARR (64 * APAD * 2)        // 9216 B per KV array
#define A_KSTAGE (4 * A_KARR)         // 36864 B per stage
#define A_KBASE (2 * A_QARR)          // 36864

__global__ __launch_bounds__(256, 1) void attn_mma(void) {
    extern __shared__ __align__(16) char sm[];
    const uint32_t sbase = smem_u32(sm);

    const int t = threadIdx.x;
    const int wid = t >> 5;
    const int lane = t & 31;
    const int h = blockIdx.y;
    const int b = blockIdx.z;
    const int q0 = blockIdx.x * 128;

    const size_t hbase = (size_t)(b * HH + h) * NN * 64;

    const int krow = t >> 2, kc16 = (t & 3) * 16;
    const uint32_t kdst = sbase + A_KBASE + (krow * APAD + kc16) * 2;
    const size_t ksrc0 = hbase + (size_t)krow * 64 + kc16;

    {
        uint32_t d = kdst;
        cp16(d, g_Kh + ksrc0); cp16(d + 16, g_Kh + ksrc0 + 8);
        cp16(d + A_KARR, g_Kl + ksrc0); cp16(d + A_KARR + 16, g_Kl + ksrc0 + 8);
        cp16(d + 2 * A_KARR, g_Vh + ksrc0); cp16(d + 2 * A_KARR + 16, g_Vh + ksrc0 + 8);
        cp16(d + 3 * A_KARR, g_Vl + ksrc0); cp16(d + 3 * A_KARR + 16, g_Vl + ksrc0 + 8);
    }
    cp_commit();

    __nv_bfloat16* const Qh = (__nv_bfloat16*)sm;
    __nv_bfloat16* const Ql = Qh + 128 * APAD;
    {
        int row = t >> 1, half = (t & 1) * 32;
        size_t src = hbase + (size_t)(q0 + row) * 64 + half;
        size_t dst = (size_t)row * APAD + half;
#pragma unroll
        for (int j = 0; j < 32; j += 8) {
            *(uint4*)(Qh + dst + j) = *(const uint4*)(g_Qh + src + j);
            *(uint4*)(Ql + dst + j) = *(const uint4*)(g_Ql + src + j);
        }
    }
    __syncthreads();

    uint32_t qfh[4][4], qfl[4][4];
    {
        const uint32_t arow = wid * 16 + (lane & 15);
        const uint32_t acoff = (lane >> 4) * 8;
#pragma unroll
        for (int ks = 0; ks < 4; ks++) {
            uint32_t off = (arow * APAD + ks * 16 + acoff) * 2;
            ldmx4(qfh[ks], sbase + off);
            ldmx4(qfl[ks], sbase + A_QARR + off);
        }
    }

    float o[8][4];
#pragma unroll
    for (int i = 0; i < 8; i++)
#pragma unroll
        for (int f = 0; f < 4; f++) o[i][f] = 0.f;
    float m0 = -1e30f, m1 = -1e30f, l0 = 0.f, l1 = 0.f;

    const uint32_t b_row = ((lane >> 4) << 3) + (lane & 7);
    const uint32_t b_coff = ((lane >> 3) & 1) * 8;
    const uint32_t v_row = ((lane >> 3) & 1) * 8 + (lane & 7);
    const uint32_t v_coff = (lane >> 4) * 8;

    int buf = 0;
    for (int kt = 0; kt < NN / 64; kt++) {
        if (kt + 1 < NN / 64) {
            uint32_t d = kdst + (buf ^ 1) * A_KSTAGE;
            size_t src = ksrc0 + (size_t)(kt + 1) * 64 * 64;
            cp16(d, g_Kh + src); cp16(d + 16, g_Kh + src + 8);
            cp16(d + A_KARR, g_Kl + src); cp16(d + A_KARR + 16, g_Kl + src + 8);
            cp16(d + 2 * A_KARR, g_Vh + src); cp16(d + 2 * A_KARR + 16, g_Vh + src + 8);
            cp16(d + 3 * A_KARR, g_Vl + src); cp16(d + 3 * A_KARR + 16, g_Vl + src + 8);
        }
        cp_commit();
        cp_wait1();
        __syncthreads();

        const uint32_t sKh = sbase + A_KBASE + buf * A_KSTAGE;
        const uint32_t sKl = sKh + A_KARR;
        const uint32_t sVh = sKh + 2 * A_KARR;
        const uint32_t sVl = sKh + 3 * A_KARR;

        float s[8][4];
#pragma unroll
        for (int i = 0; i < 8; i++)
#pragma unroll
            for (int f = 0; f < 4; f++) s[i][f] = 0.f;
#pragma unroll
        for (int ks = 0; ks < 4; ks++) {
            const uint32_t kc = ks * 16;
#pragma unroll
            for (int g = 0; g < 4; g++) {
                uint32_t bh[4], bl[4];
                uint32_t off = ((g * 16 + b_row) * APAD + kc + b_coff) * 2;
                ldmx4(bh, sKh + off);
                ldmx4(bl, sKl + off);
                mma_bf16(s[2 * g],     qfh[ks], &bh[0]);
                mma_bf16(s[2 * g],     qfh[ks], &bl[0]);
                mma_bf16(s[2 * g],     qfl[ks], &bh[0]);
                mma_bf16(s[2 * g + 1], qfh[ks], &bh[2]);
                mma_bf16(s[2 * g + 1], qfh[ks], &bl[2]);
                mma_bf16(s[2 * g + 1], qfl[ks], &bh[2]);
            }
        }

        float tm0 = -1e30f, tm1 = -1e30f;
#pragma unroll
        for (int nt = 0; nt < 8; nt++) {
            tm0 = fmaxf(tm0, fmaxf(s[nt][0], s[nt][1]));
            tm1 = fmaxf(tm1, fmaxf(s[nt][2], s[nt][3]));
        }
        tm0 = fmaxf(tm0, __shfl_xor_sync(0xffffffffu, tm0, 1));
        tm0 = fmaxf(tm0, __shfl_xor_sync(0xffffffffu, tm0, 2));
        tm1 = fmaxf(tm1, __shfl_xor_sync(0xffffffffu, tm1, 1));
        tm1 = fmaxf(tm1, __shfl_xor_sync(0xffffffffu, tm1, 2));
        float mn0 = fmaxf(m0, tm0), mn1 = fmaxf(m1, tm1);
        float al0 = exp2f(m0 - mn0), al1 = exp2f(m1 - mn1);
        m0 = mn0; m1 = mn1;
        float rs0 = 0.f, rs1 = 0.f;
#pragma unroll
        for (int nt = 0; nt < 8; nt++) {
            s[nt][0] = exp2f(s[nt][0] - m0);
            s[nt][1] = exp2f(s[nt][1] - m0);
            s[nt][2] = exp2f(s[nt][2] - m1);
            s[nt][3] = exp2f(s[nt][3] - m1);
            rs0 += s[nt][0] + s[nt][1];
            rs1 += s[nt][2] + s[nt][3];
        }
        l0 = l0 * al0 + rs0;
        l1 = l1 * al1 + rs1;
#pragma unroll
        for (int nt = 0; nt < 8; nt++) {
            o[nt][0] *= al0; o[nt][1] *= al0;
            o[nt][2] *= al1; o[nt][3] *= al1;
        }

        uint32_t ph[4][4], pl[4][4];
#pragma unroll
        for (int ks = 0; ks < 4; ks++) {
#pragma unroll
            for (int hf = 0; hf < 2; hf++) {
                int nt = 2 * ks + hf;
                split2(s[nt][0], s[nt][1], ph[ks][hf * 2 + 0], pl[ks][hf * 2 + 0]);
                split2(s[nt][2], s[nt][3], ph[ks][hf * 2 + 1], pl[ks][hf * 2 + 1]);
            }
        }

#pragma unroll
        for (int ks = 0; ks < 4; ks++) {
            const uint32_t kr = ks * 16 + v_row;
#pragma unroll
            for (int g = 0; g < 4; g++) {
                uint32_t vh4[4], vl4[4];
                uint32_t off = (kr * APAD + g * 16 + v_coff) * 2;
                ldmx4t(vh4, sVh + off);
                ldmx4t(vl4, sVl + off);
                mma_bf16(o[2 * g],     ph[ks], &vh4[0]);
                mma_bf16(o[2 * g],     ph[ks], &vl4[0]);
                mma_bf16(o[2 * g],     pl[ks], &vh4[0]);
                mma_bf16(o[2 * g + 1], ph[ks], &vh4[2]);
                mma_bf16(o[2 * g + 1], ph[ks], &vl4[2]);
                mma_bf16(o[2 * g + 1], pl[ks], &vh4[2]);
            }
        }
        __syncthreads();
        buf ^= 1;
    }

    // ---- epilogue: reduce l, write plain fp32 to g_attn ----
    l0 += __shfl_xor_sync(0xffffffffu, l0, 1);
    l0 += __shfl_xor_sync(0xffffffffu, l0, 2);
    l1 += __shfl_xor_sync(0xffffffffu, l1, 1);
    l1 += __shfl_xor_sync(0xffffffffu, l1, 2);
    float inv0 = 1.f / l0, inv1 = 1.f / l1;
    int r0 = q0 + wid * 16 + (lane >> 2);
    int cbase = (lane & 3) * 2;
    float* op0 = g_attn + (size_t)(b * NN + r0) * CC + h * DD + cbase;
    float* op1 = op0 + (size_t)8 * CC;
#pragma unroll
    for (int nt = 0; nt < 8; nt++) {
        *(float2*)(op0 + nt * 8) = make_float2(o[nt][0] * inv0, o[nt][1] * inv0);
        *(float2*)(op1 + nt * 8) = make_float2(o[nt][2] * inv1, o[nt][3] * inv1);
    }
}

// ---------------------------------------------------------------------------
extern "C" void kernel_launch(void* const* d_in, const int* in_sizes, int n_in,
                              void* d_out, int out_size) {
    const float* x      = (const float*)d_in[0];
    const float* freqs  = (const float*)d_in[1];
    const float* w_qkv  = (const float*)d_in[2];
    const float* w_proj = (const float*)d_in[3];
    const float* b_proj = (const float*)d_in[4];
    float* out = (float*)d_out;

    float *qkv, *attn;
    cudaGetSymbolAddress((void**)&qkv, g_qkv);
    cudaGetSymbolAddress((void**)&attn, g_attn);

    static int init_done = 0;
    if (!init_done) {
        cudaFuncSetAttribute(gemm_tf32, cudaFuncAttributeMaxDynamicSharedMemorySize,
                             2 * GF_STAGE);
        cudaFuncSetAttribute(attn_mma, cudaFuncAttributeMaxDynamicSharedMemorySize,
                             A_KBASE + 2 * A_KSTAGE);
        init_done = 1;
    }

    // 1) qkv = x @ w_qkv^T   (tf32 single-pass, raw fp32 staging)
    gemm_tf32<<<dim3(3 * CC / 128, MR / 128), 256, 2 * GF_STAGE>>>(
        x, w_qkv, nullptr, qkv, MR, 3 * CC, CC);
    // 2) RoPE + split q/k/v (head-contiguous; q pre-scaled for exp2 domain)
    prep_qkv<<<(BB * NN * HH * 2) / 256, 256>>>(qkv, freqs);
    // 3) attention (bf16 3-term; outputs fp32 g_attn)
    attn_mma<<<dim3(NN / 128, HH, BB), 256, A_KBASE + 2 * A_KSTAGE>>>();
    // 4) out = attn @ w_proj^T + b_proj   (tf32 single-pass)
    gemm_tf32<<<dim3(CC / 128, MR / 128), 256, 2 * GF_STAGE>>>(
        attn, w_proj, b_proj, out, MR, CC, CC);
}

// round 16
// speedup vs baseline: 1.1100x; 1.0066x over previous
#include <cuda_runtime.h>
#include <cuda_bf16.h>
#include <math.h>
#include <stdint.h>

#define BB 2
#define NN 2048
#define CC 1024
#define HH 16
#define DD 64
#define MR (BB*NN)          // 4096 rows
#define QK_SCALE 0.125f     // 64^-0.5
#define LOG2E 1.4426950408889634f

// ---- global scratch (allocation-free rule) --------------------------------
__device__ float g_qkv[(size_t)MR * 3 * CC];    // fp32 qkv (gemm1 out)
__device__ float g_attn[(size_t)MR * CC];       // fp32 attn out (gemm2 in)
// tf32-rounded fp32, head-contiguous; Q pre-scaled by SCALE*log2e
__device__ float g_Q[(size_t)MR * CC];          // [bh][n][64]
__device__ float g_K[(size_t)MR * CC];          // [bh][n][64]
__device__ float g_Vt[(size_t)MR * CC];         // [bh][d][NN]  (V transposed)

// ---- helpers --------------------------------------------------------------
__device__ __forceinline__ uint32_t smem_u32(const void* p) {
    return (uint32_t)__cvta_generic_to_shared(p);
}
__device__ __forceinline__ void cp16(uint32_t dst, const void* src) {
    asm volatile("cp.async.ca.shared.global [%0], [%1], 16;"
                 :: "r"(dst), "l"(src) : "memory");
}
__device__ __forceinline__ void cp_commit() {
    asm volatile("cp.async.commit_group;" ::: "memory");
}
__device__ __forceinline__ void cp_wait1() {
    asm volatile("cp.async.wait_group 1;" ::: "memory");
}
__device__ __forceinline__ void ldmx4(uint32_t* r, uint32_t addr) {
    asm volatile("ldmatrix.sync.aligned.m8n8.x4.shared.b16 {%0,%1,%2,%3}, [%4];"
                 : "=r"(r[0]), "=r"(r[1]), "=r"(r[2]), "=r"(r[3]) : "r"(addr));
}
__device__ __forceinline__ void mma_tf32(float* c, const uint32_t* a, const uint32_t* b) {
    asm volatile(
        "mma.sync.aligned.m16n8k8.row.col.f32.tf32.tf32.f32 "
        "{%0,%1,%2,%3}, {%4,%5,%6,%7}, {%8,%9}, {%0,%1,%2,%3};"
        : "+f"(c[0]), "+f"(c[1]), "+f"(c[2]), "+f"(c[3])
        : "r"(a[0]), "r"(a[1]), "r"(a[2]), "r"(a[3]), "r"(b[0]), "r"(b[1]));
}
__device__ __forceinline__ void cvt_tf32x4(uint32_t* r) {
#pragma unroll
    for (int i = 0; i < 4; i++) {
        float f = __uint_as_float(r[i]);
        asm volatile("cvt.rna.tf32.f32 %0, %1;" : "=r"(r[i]) : "f"(f));
    }
}
__device__ __forceinline__ float cvt1(float f) {
    uint32_t r;
    asm volatile("cvt.rna.tf32.f32 %0, %1;" : "=r"(r) : "f"(f));
    return __uint_as_float(r);
}

// ---------------------------------------------------------------------------
// prep: RoPE q/k, q scaled by QK_SCALE*log2e, tf32-round, fp32 out [bh][n][64]
// ---------------------------------------------------------------------------
__global__ void prep_qkv(const float* __restrict__ qkv,
                         const float* __restrict__ freqs) {
    int gid = blockIdx.x * blockDim.x + threadIdx.x;
    int half = gid & 1;
    int h = (gid >> 1) & (HH - 1);
    int n = (gid >> 5) & (NN - 1);
    int b = gid >> 16;

    const float* base = qkv + (size_t)(b * NN + n) * 3 * CC + h * DD + half * 32;
    const float* fp = freqs + (size_t)n * 32 + half * 16;
    size_t orow = ((size_t)(b * HH + h) * NN + n) * 64 + half * 32;
    const float QS = QK_SCALE * LOG2E;

#pragma unroll
    for (int j = 0; j < 32; j += 4) {
        float c0, s0, c1, s1;
        __sincosf(fp[j / 2], &s0, &c0);
        __sincosf(fp[j / 2 + 1], &s1, &c1);

        float4 q = *(const float4*)(base + j);
        float4 oq;
        oq.x = cvt1((q.x * c0 - q.y * s0) * QS);
        oq.y = cvt1((q.x * s0 + q.y * c0) * QS);
        oq.z = cvt1((q.z * c1 - q.w * s1) * QS);
        oq.w = cvt1((q.z * s1 + q.w * c1) * QS);
        *(float4*)(g_Q + orow + j) = oq;

        float4 k = *(const float4*)(base + CC + j);
        float4 ok;
        ok.x = cvt1(k.x * c0 - k.y * s0);
        ok.y = cvt1(k.x * s0 + k.y * c0);
        ok.z = cvt1(k.z * c1 - k.w * s1);
        ok.w = cvt1(k.z * s1 + k.w * c1);
        *(float4*)(g_K + orow + j) = ok;
    }
}

// ---------------------------------------------------------------------------
// prep_vt: transpose V [n][d] -> g_Vt [bh][d][n], tf32-rounded.
// 32x32 tiles via smem. grid (NN/32, 2, BB*HH), 256 threads.
// ---------------------------------------------------------------------------
__global__ void prep_vt(const float* __restrict__ qkv) {
    __shared__ float ts[32][33];
    int bh = blockIdx.z;
    int b = bh >> 4, h = bh & 15;
    int n0 = blockIdx.x * 32, d0 = blockIdx.y * 32;
    int t = threadIdx.x;

    {   // load: lanes span d (coalesced), 8 n per pass
        int d = t & 31, nn = t >> 5;
        const float* src = qkv + (size_t)(b * NN + n0 + nn) * 3 * CC
                           + 2 * CC + h * DD + d0 + d;
#pragma unroll
        for (int i = 0; i < 4; i++)
            ts[d][nn + i * 8] = src[(size_t)(i * 8) * 3 * CC];
    }
    __syncthreads();
    {   // store: lanes span n (coalesced), 8 d per pass
        int n = t & 31, dd = t >> 5;
        float* dst = g_Vt + (size_t)bh * DD * NN + (size_t)(d0 + dd) * NN + n0 + n;
#pragma unroll
        for (int i = 0; i < 4; i++)
            dst[(size_t)(i * 8) * NN] = cvt1(ts[dd + i * 8][n]);
    }
}

// ---------------------------------------------------------------------------
// tf32 GEMM (round-15 proven): CTA 128x128, K-chunk 32 (4 x k8), 8 warps
// (64x32 warp tile), cp.async double-buffered fp32, cvt.rna in-reg, 2 CTA/SM.
// ---------------------------------------------------------------------------
#define SPADF 36                      // floats per smem row (32 data + 4 pad)
#define GF_ARR (128 * SPADF * 4)      // 18432 B per array
#define GF_STAGE (2 * GF_ARR)         // 36864 B per stage

__global__ __launch_bounds__(256, 2) void gemm_tf32(
        const float* __restrict__ A, const float* __restrict__ W,
        const float* __restrict__ bias, float* __restrict__ Cm,
        int M, int Nc, int K) {
    extern __shared__ __align__(16) char sm[];
    const uint32_t sbase = smem_u32(sm);

    const int tid = threadIdx.x;
    const int wid = tid >> 5;
    const int lane = tid & 31;
    const int m0 = blockIdx.y * 128;
    const int n0 = blockIdx.x * 128;
    const int wm = (wid >> 2) * 64;
    const int wn = (wid & 3) * 32;

    const int lrow = tid >> 1;
    const int lcolf = (tid & 1) * 16;
    const float* Ap = A + (size_t)(m0 + lrow) * K + lcolf;
    const float* Wp = W + (size_t)(n0 + lrow) * K + lcolf;
    const uint32_t adst = sbase + (lrow * SPADF + lcolf) * 4;
    const uint32_t bdst = adst + GF_ARR;

    float acc[4][4][4];
#pragma unroll
    for (int i = 0; i < 4; i++)
#pragma unroll
        for (int j = 0; j < 4; j++)
#pragma unroll
            for (int f = 0; f < 4; f++) acc[i][j][f] = 0.f;

    const uint32_t a_row = wm + (lane & 15);
    const uint32_t a_coff = (lane >> 4) * 4;
    const uint32_t b_row = wn + ((lane >> 4) << 3) + (lane & 7);
    const uint32_t b_coff = ((lane >> 3) & 1) * 4;

#pragma unroll
    for (int c = 0; c < 4; c++) {
        cp16(adst + c * 16, Ap + c * 4);
        cp16(bdst + c * 16, Wp + c * 4);
    }
    cp_commit();

    int buf = 0;
    for (int k0 = 0; k0 < K; k0 += 32) {
        if (k0 + 32 < K) {
            uint32_t d = (buf ^ 1) * GF_STAGE;
            int kn = k0 + 32;
#pragma unroll
            for (int c = 0; c < 4; c++) {
                cp16(adst + d + c * 16, Ap + kn + c * 4);
                cp16(bdst + d + c * 16, Wp + kn + c * 4);
            }
        }
        cp_commit();
        cp_wait1();
        __syncthreads();

        const uint32_t sA = sbase + buf * GF_STAGE;
        const uint32_t sB = sA + GF_ARR;

#pragma unroll
        for (int ks = 0; ks < 4; ks++) {
            const uint32_t kc = ks * 8;
            uint32_t af[4][4];
#pragma unroll
            for (int mt = 0; mt < 4; mt++) {
                ldmx4(af[mt], sA + ((a_row + mt * 16) * SPADF + kc + a_coff) * 4);
                cvt_tf32x4(af[mt]);
            }
            uint32_t bf[2][4];
#pragma unroll
            for (int p = 0; p < 2; p++) {
                ldmx4(bf[p], sB + ((b_row + p * 16) * SPADF + kc + b_coff) * 4);
                cvt_tf32x4(bf[p]);
            }
#pragma unroll
            for (int mt = 0; mt < 4; mt++)
#pragma unroll
                for (int p = 0; p < 2; p++) {
                    mma_tf32(acc[mt][2 * p],     af[mt], &bf[p][0]);
                    mma_tf32(acc[mt][2 * p + 1], af[mt], &bf[p][2]);
                }
        }
        __syncthreads();
        buf ^= 1;
    }

    const int erow = lane >> 2;
    const int ecol = (lane & 3) * 2;
#pragma unroll
    for (int mt = 0; mt < 4; mt++) {
#pragma unroll
        for (int nt = 0; nt < 4; nt++) {
            int gr = m0 + wm + mt * 16 + erow;
            int gc = n0 + wn + nt * 8 + ecol;
            float b0 = 0.f, b1 = 0.f;
            if (bias) { b0 = bias[gc]; b1 = bias[gc + 1]; }
            *(float2*)(Cm + (size_t)gr * Nc + gc) =
                make_float2(acc[mt][nt][0] + b0, acc[mt][nt][1] + b1);
            *(float2*)(Cm + (size_t)(gr + 8) * Nc + gc) =
                make_float2(acc[mt][nt][2] + b0, acc[mt][nt][3] + b1);
        }
    }
}

// ---------------------------------------------------------------------------
// Flash attention, tf32 single-pass.
// 128 q-rows, 256 threads, 8 warps. K/Vt fp32 (pre-rounded) double-buffered.
// P routed through smem (reuses Q region) with cvt.rna on reload.
// smem: Q/P 128x68 f32 (34816) + 2 x (K 64x68 + Vt 64x68) = 104448 B.
// ---------------------------------------------------------------------------
#define QPAD 68
#define A_QREG (128 * QPAD * 4)       // 34816 B (Q, later P)
#define A_KARR (64 * QPAD * 4)        // 17408 B
#define A_KSTAGE (2 * A_KARR)         // 34816 B
#define A_KBASE A_QREG

__global__ __launch_bounds__(256, 1) void attn_tf32(void) {
    extern __shared__ __align__(16) char sm[];
    const uint32_t sbase = smem_u32(sm);
    float* const Ps = (float*)sm;

    const int t = threadIdx.x;
    const int wid = t >> 5;
    const int lane = t & 31;
    const int h = blockIdx.y;
    const int b = blockIdx.z;
    const int bh = b * HH + h;
    const int q0 = blockIdx.x * 128;

    const size_t hbase = (size_t)bh * NN * 64;     // g_Q/g_K base
    const size_t vtbase = (size_t)bh * DD * NN;    // g_Vt base

    // staging map: row = t>>2 (key or d), seg = (t&3)*16 floats
    const int srow = t >> 2, sseg = (t & 3) * 16;
    const uint32_t kdst = sbase + A_KBASE + (srow * QPAD + sseg) * 4;
    const uint32_t vdst = kdst + A_KARR;
    const float* ksrc0 = g_K + hbase + (size_t)srow * 64 + sseg;
    const float* vsrc0 = g_Vt + vtbase + (size_t)srow * NN + sseg;

    // prefetch K/V block 0
#pragma unroll
    for (int c = 0; c < 4; c++) {
        cp16(kdst + c * 16, ksrc0 + c * 4);
        cp16(vdst + c * 16, vsrc0 + c * 4);
    }
    cp_commit();

    // stage Q [128][QPAD] f32
    {
        int row = t >> 1, half = (t & 1) * 32;
        const float* src = g_Q + hbase + (size_t)(q0 + row) * 64 + half;
        float* dst = (float*)sm + row * QPAD + half;
#pragma unroll
        for (int j = 0; j < 32; j += 4)
            *(float4*)(dst + j) = *(const float4*)(src + j);
    }
    __syncthreads();

    // Q fragments (8 x k8), held in registers for the whole kernel
    const uint32_t arow = wid * 16 + (lane & 15);
    const uint32_t acoff = (lane >> 4) * 4;
    uint32_t qf[8][4];
#pragma unroll
    for (int ks = 0; ks < 8; ks++)
        ldmx4(qf[ks], sbase + (arow * QPAD + ks * 8 + acoff) * 4);

    float o[8][4];
#pragma unroll
    for (int i = 0; i < 8; i++)
#pragma unroll
        for (int f = 0; f < 4; f++) o[i][f] = 0.f;
    float m0 = -1e30f, m1 = -1e30f, l0 = 0.f, l1 = 0.f;

    const uint32_t b_row = ((lane >> 4) << 3) + (lane & 7);
    const uint32_t b_coff = ((lane >> 3) & 1) * 4;
    const int prow = lane >> 2;
    const int pcol = 2 * (lane & 3);

    int buf = 0;
    for (int kt = 0; kt < NN / 64; kt++) {
        if (kt + 1 < NN / 64) {
            uint32_t d = (buf ^ 1) * A_KSTAGE;
            const float* ks_ = ksrc0 + (size_t)(kt + 1) * 64 * 64;
            const float* vs_ = vsrc0 + (kt + 1) * 64;
#pragma unroll
            for (int c = 0; c < 4; c++) {
                cp16(kdst + d + c * 16, ks_ + c * 4);
                cp16(vdst + d + c * 16, vs_ + c * 4);
            }
        }
        cp_commit();
        cp_wait1();
        __syncthreads();   // staging visible; also orders prev PV reads vs P STS

        const uint32_t sK = sbase + A_KBASE + buf * A_KSTAGE;
        const uint32_t sVt = sK + A_KARR;

        // ---- S = Q.K^T (log2 domain), tf32 ----
        float s[8][4];
#pragma unroll
        for (int i = 0; i < 8; i++)
#pragma unroll
            for (int f = 0; f < 4; f++) s[i][f] = 0.f;
#pragma unroll
        for (int ks = 0; ks < 8; ks++) {
            const uint32_t kc = ks * 8;
#pragma unroll
            for (int g = 0; g < 4; g++) {
                uint32_t bf[4];
                ldmx4(bf, sK + ((g * 16 + b_row) * QPAD + kc + b_coff) * 4);
                mma_tf32(s[2 * g],     qf[ks], &bf[0]);
                mma_tf32(s[2 * g + 1], qf[ks], &bf[2]);
            }
        }

        // ---- online softmax (exp2 domain; l lane-partial) ----
        float tm0 = -1e30f, tm1 = -1e30f;
#pragma unroll
        for (int nt = 0; nt < 8; nt++) {
            tm0 = fmaxf(tm0, fmaxf(s[nt][0], s[nt][1]));
            tm1 = fmaxf(tm1, fmaxf(s[nt][2], s[nt][3]));
        }
        tm0 = fmaxf(tm0, __shfl_xor_sync(0xffffffffu, tm0, 1));
        tm0 = fmaxf(tm0, __shfl_xor_sync(0xffffffffu, tm0, 2));
        tm1 = fmaxf(tm1, __shfl_xor_sync(0xffffffffu, tm1, 1));
        tm1 = fmaxf(tm1, __shfl_xor_sync(0xffffffffu, tm1, 2));
        float mn0 = fmaxf(m0, tm0), mn1 = fmaxf(m1, tm1);
        float al0 = exp2f(m0 - mn0), al1 = exp2f(m1 - mn1);
        m0 = mn0; m1 = mn1;
        float rs0 = 0.f, rs1 = 0.f;
#pragma unroll
        for (int nt = 0; nt < 8; nt++) {
            s[nt][0] = exp2f(s[nt][0] - m0);
            s[nt][1] = exp2f(s[nt][1] - m0);
            s[nt][2] = exp2f(s[nt][2] - m1);
            s[nt][3] = exp2f(s[nt][3] - m1);
            rs0 += s[nt][0] + s[nt][1];
            rs1 += s[nt][2] + s[nt][3];
        }
        l0 = l0 * al0 + rs0;
        l1 = l1 * al1 + rs1;
#pragma unroll
        for (int nt = 0; nt < 8; nt++) {
            o[nt][0] *= al0; o[nt][1] *= al0;
            o[nt][2] *= al1; o[nt][3] *= al1;
        }

        // ---- P -> smem (Q region), then A-fragments via ldmatrix ----
        {
            int r = wid * 16 + prow;
#pragma unroll
            for (int nt = 0; nt < 8; nt++) {
                *(float2*)&Ps[(r) * QPAD + nt * 8 + pcol] =
                    make_float2(s[nt][0], s[nt][1]);
                *(float2*)&Ps[(r + 8) * QPAD + nt * 8 + pcol] =
                    make_float2(s[nt][2], s[nt][3]);
            }
        }
        __syncthreads();

        // ---- O += P.V, tf32 (Vt: rows=d, cols=keys) ----
#pragma unroll
        for (int ks = 0; ks < 8; ks++) {
            uint32_t pf[4];
            ldmx4(pf, sbase + (arow * QPAD + ks * 8 + acoff) * 4);
            cvt_tf32x4(pf);
            const uint32_t kc = ks * 8;
#pragma unroll
            for (int g = 0; g < 4; g++) {
                uint32_t vf[4];
                ldmx4(vf, sVt + ((g * 16 + b_row) * QPAD + kc + b_coff) * 4);
                mma_tf32(o[2 * g],     pf, &vf[0]);
                mma_tf32(o[2 * g + 1], pf, &vf[2]);
            }
        }
        buf ^= 1;
    }

    // ---- epilogue: reduce l, write fp32 g_attn ----
    l0 += __shfl_xor_sync(0xffffffffu, l0, 1);
    l0 += __shfl_xor_sync(0xffffffffu, l0, 2);
    l1 += __shfl_xor_sync(0xffffffffu, l1, 1);
    l1 += __shfl_xor_sync(0xffffffffu, l1, 2);
    float inv0 = 1.f / l0, inv1 = 1.f / l1;
    int r0 = q0 + wid * 16 + (lane >> 2);
    int cbase = (lane & 3) * 2;
    float* op0 = g_attn + (size_t)(b * NN + r0) * CC + h * DD + cbase;
    float* op1 = op0 + (size_t)8 * CC;
#pragma unroll
    for (int nt = 0; nt < 8; nt++) {
        *(float2*)(op0 + nt * 8) = make_float2(o[nt][0] * inv0, o[nt][1] * inv0);
        *(float2*)(op1 + nt * 8) = make_float2(o[nt][2] * inv1, o[nt][3] * inv1);
    }
}

// ---------------------------------------------------------------------------
extern "C" void kernel_launch(void* const* d_in, const int* in_sizes, int n_in,
                              void* d_out, int out_size) {
    const float* x      = (const float*)d_in[0];
    const float* freqs  = (const float*)d_in[1];
    const float* w_qkv  = (const float*)d_in[2];
    const float* w_proj = (const float*)d_in[3];
    const float* b_proj = (const float*)d_in[4];
    float* out = (float*)d_out;

    float *qkv, *attn;
    cudaGetSymbolAddress((void**)&qkv, g_qkv);
    cudaGetSymbolAddress((void**)&attn, g_attn);

    static int init_done = 0;
    if (!init_done) {
        cudaFuncSetAttribute(gemm_tf32, cudaFuncAttributeMaxDynamicSharedMemorySize,
                             2 * GF_STAGE);
        cudaFuncSetAttribute(attn_tf32, cudaFuncAttributeMaxDynamicSharedMemorySize,
                             A_QREG + 2 * A_KSTAGE);
        init_done = 1;
    }

    // 1) qkv = x @ w_qkv^T   (tf32 single-pass)
    gemm_tf32<<<dim3(3 * CC / 128, MR / 128), 256, 2 * GF_STAGE>>>(
        x, w_qkv, nullptr, qkv, MR, 3 * CC, CC);
    // 2) RoPE + tf32-round Q/K (head-contiguous); transpose + round V
    prep_qkv<<<(BB * NN * HH * 2) / 256, 256>>>(qkv, freqs);
    prep_vt<<<dim3(NN / 32, DD / 32, BB * HH), 256>>>(qkv);
    // 3) attention, tf32 single-pass (outputs fp32 g_attn)
    attn_tf32<<<dim3(NN / 128, HH, BB), 256, A_QREG + 2 * A_KSTAGE>>>();
    // 4) out = attn @ w_proj^T + b_proj   (tf32 single-pass)
    gemm_tf32<<<dim3(CC / 128, MR / 128), 256, 2 * GF_STAGE>>>(
        attn, w_proj, b_proj, out, MR, CC, CC);
}

// round 17
// speedup vs baseline: 1.1507x; 1.0367x over previous
#include <cuda_runtime.h>
#include <cuda_bf16.h>
#include <math.h>
#include <stdint.h>

#define BB 2
#define NN 2048
#define CC 1024
#define HH 16
#define DD 64
#define MR (BB*NN)          // 4096 rows
#define QK_SCALE 0.125f     // 64^-0.5
#define LOG2E 1.4426950408889634f

// ---- global scratch (allocation-free rule) --------------------------------
__device__ float g_qkv[(size_t)MR * 3 * CC];    // fp32 qkv (gemm1 out)
__device__ float g_attn[(size_t)MR * CC];       // fp32 attn out (gemm2 in)
// tf32-rounded fp32, head-contiguous; Q pre-scaled by SCALE*log2e
__device__ float g_Q[(size_t)MR * CC];          // [bh][n][64]
__device__ float g_K[(size_t)MR * CC];          // [bh][n][64]
__device__ float g_Vt[(size_t)MR * CC];         // [bh][d][NN]  (V transposed)

// ---- helpers --------------------------------------------------------------
__device__ __forceinline__ uint32_t smem_u32(const void* p) {
    return (uint32_t)__cvta_generic_to_shared(p);
}
__device__ __forceinline__ void cp16(uint32_t dst, const void* src) {
    asm volatile("cp.async.ca.shared.global [%0], [%1], 16;"
                 :: "r"(dst), "l"(src) : "memory");
}
__device__ __forceinline__ void cp_commit() {
    asm volatile("cp.async.commit_group;" ::: "memory");
}
__device__ __forceinline__ void cp_wait1() {
    asm volatile("cp.async.wait_group 1;" ::: "memory");
}
__device__ __forceinline__ void ldmx4(uint32_t* r, uint32_t addr) {
    asm volatile("ldmatrix.sync.aligned.m8n8.x4.shared.b16 {%0,%1,%2,%3}, [%4];"
                 : "=r"(r[0]), "=r"(r[1]), "=r"(r[2]), "=r"(r[3]) : "r"(addr));
}
__device__ __forceinline__ void mma_tf32(float* c, const uint32_t* a, const uint32_t* b) {
    asm volatile(
        "mma.sync.aligned.m16n8k8.row.col.f32.tf32.tf32.f32 "
        "{%0,%1,%2,%3}, {%4,%5,%6,%7}, {%8,%9}, {%0,%1,%2,%3};"
        : "+f"(c[0]), "+f"(c[1]), "+f"(c[2]), "+f"(c[3])
        : "r"(a[0]), "r"(a[1]), "r"(a[2]), "r"(a[3]), "r"(b[0]), "r"(b[1]));
}
__device__ __forceinline__ void cvt_tf32x4(uint32_t* r) {
#pragma unroll
    for (int i = 0; i < 4; i++) {
        float f = __uint_as_float(r[i]);
        asm volatile("cvt.rna.tf32.f32 %0, %1;" : "=r"(r[i]) : "f"(f));
    }
}
__device__ __forceinline__ float cvt1(float f) {
    uint32_t r;
    asm volatile("cvt.rna.tf32.f32 %0, %1;" : "=r"(r) : "f"(f));
    return __uint_as_float(r);
}
__device__ __forceinline__ uint32_t cvt1u(float f) {
    uint32_t r;
    asm volatile("cvt.rna.tf32.f32 %0, %1;" : "=r"(r) : "f"(f));
    return r;
}

// ---------------------------------------------------------------------------
// prep: RoPE q/k, q scaled by QK_SCALE*log2e, tf32-round, fp32 out [bh][n][64]
// ---------------------------------------------------------------------------
__global__ void prep_qkv(const float* __restrict__ qkv,
                         const float* __restrict__ freqs) {
    int gid = blockIdx.x * blockDim.x + threadIdx.x;
    int half = gid & 1;
    int h = (gid >> 1) & (HH - 1);
    int n = (gid >> 5) & (NN - 1);
    int b = gid >> 16;

    const float* base = qkv + (size_t)(b * NN + n) * 3 * CC + h * DD + half * 32;
    const float* fp = freqs + (size_t)n * 32 + half * 16;
    size_t orow = ((size_t)(b * HH + h) * NN + n) * 64 + half * 32;
    const float QS = QK_SCALE * LOG2E;

#pragma unroll
    for (int j = 0; j < 32; j += 4) {
        float c0, s0, c1, s1;
        __sincosf(fp[j / 2], &s0, &c0);
        __sincosf(fp[j / 2 + 1], &s1, &c1);

        float4 q = *(const float4*)(base + j);
        float4 oq;
        oq.x = cvt1((q.x * c0 - q.y * s0) * QS);
        oq.y = cvt1((q.x * s0 + q.y * c0) * QS);
        oq.z = cvt1((q.z * c1 - q.w * s1) * QS);
        oq.w = cvt1((q.z * s1 + q.w * c1) * QS);
        *(float4*)(g_Q + orow + j) = oq;

        float4 k = *(const float4*)(base + CC + j);
        float4 ok;
        ok.x = cvt1(k.x * c0 - k.y * s0);
        ok.y = cvt1(k.x * s0 + k.y * c0);
        ok.z = cvt1(k.z * c1 - k.w * s1);
        ok.w = cvt1(k.z * s1 + k.w * c1);
        *(float4*)(g_K + orow + j) = ok;
    }
}

// ---------------------------------------------------------------------------
// prep_vt: transpose V [n][d] -> g_Vt [bh][d][n], tf32-rounded.
// ---------------------------------------------------------------------------
__global__ void prep_vt(const float* __restrict__ qkv) {
    __shared__ float ts[32][33];
    int bh = blockIdx.z;
    int b = bh >> 4, h = bh & 15;
    int n0 = blockIdx.x * 32, d0 = blockIdx.y * 32;
    int t = threadIdx.x;

    {
        int d = t & 31, nn = t >> 5;
        const float* src = qkv + (size_t)(b * NN + n0 + nn) * 3 * CC
                           + 2 * CC + h * DD + d0 + d;
#pragma unroll
        for (int i = 0; i < 4; i++)
            ts[d][nn + i * 8] = src[(size_t)(i * 8) * 3 * CC];
    }
    __syncthreads();
    {
        int n = t & 31, dd = t >> 5;
        float* dst = g_Vt + (size_t)bh * DD * NN + (size_t)(d0 + dd) * NN + n0 + n;
#pragma unroll
        for (int i = 0; i < 4; i++)
            dst[(size_t)(i * 8) * NN] = cvt1(ts[dd + i * 8][n]);
    }
}

// ---------------------------------------------------------------------------
// tf32 GEMM (round-15 proven): CTA 128x128, K-chunk 32 (4 x k8), 8 warps
// (64x32 warp tile), cp.async double-buffered fp32, cvt.rna in-reg, 2 CTA/SM.
// ---------------------------------------------------------------------------
#define SPADF 36
#define GF_ARR (128 * SPADF * 4)
#define GF_STAGE (2 * GF_ARR)

__global__ __launch_bounds__(256, 2) void gemm_tf32(
        const float* __restrict__ A, const float* __restrict__ W,
        const float* __restrict__ bias, float* __restrict__ Cm,
        int M, int Nc, int K) {
    extern __shared__ __align__(16) char sm[];
    const uint32_t sbase = smem_u32(sm);

    const int tid = threadIdx.x;
    const int wid = tid >> 5;
    const int lane = tid & 31;
    const int m0 = blockIdx.y * 128;
    const int n0 = blockIdx.x * 128;
    const int wm = (wid >> 2) * 64;
    const int wn = (wid & 3) * 32;

    const int lrow = tid >> 1;
    const int lcolf = (tid & 1) * 16;
    const float* Ap = A + (size_t)(m0 + lrow) * K + lcolf;
    const float* Wp = W + (size_t)(n0 + lrow) * K + lcolf;
    const uint32_t adst = sbase + (lrow * SPADF + lcolf) * 4;
    const uint32_t bdst = adst + GF_ARR;

    float acc[4][4][4];
#pragma unroll
    for (int i = 0; i < 4; i++)
#pragma unroll
        for (int j = 0; j < 4; j++)
#pragma unroll
            for (int f = 0; f < 4; f++) acc[i][j][f] = 0.f;

    const uint32_t a_row = wm + (lane & 15);
    const uint32_t a_coff = (lane >> 4) * 4;
    const uint32_t b_row = wn + ((lane >> 4) << 3) + (lane & 7);
    const uint32_t b_coff = ((lane >> 3) & 1) * 4;

#pragma unroll
    for (int c = 0; c < 4; c++) {
        cp16(adst + c * 16, Ap + c * 4);
        cp16(bdst + c * 16, Wp + c * 4);
    }
    cp_commit();

    int buf = 0;
    for (int k0 = 0; k0 < K; k0 += 32) {
        if (k0 + 32 < K) {
            uint32_t d = (buf ^ 1) * GF_STAGE;
            int kn = k0 + 32;
#pragma unroll
            for (int c = 0; c < 4; c++) {
                cp16(adst + d + c * 16, Ap + kn + c * 4);
                cp16(bdst + d + c * 16, Wp + kn + c * 4);
            }
        }
        cp_commit();
        cp_wait1();
        __syncthreads();

        const uint32_t sA = sbase + buf * GF_STAGE;
        const uint32_t sB = sA + GF_ARR;

#pragma unroll
        for (int ks = 0; ks < 4; ks++) {
            const uint32_t kc = ks * 8;
            uint32_t af[4][4];
#pragma unroll
            for (int mt = 0; mt < 4; mt++) {
                ldmx4(af[mt], sA + ((a_row + mt * 16) * SPADF + kc + a_coff) * 4);
                cvt_tf32x4(af[mt]);
            }
            uint32_t bf[2][4];
#pragma unroll
            for (int p = 0; p < 2; p++) {
                ldmx4(bf[p], sB + ((b_row + p * 16) * SPADF + kc + b_coff) * 4);
                cvt_tf32x4(bf[p]);
            }
#pragma unroll
            for (int mt = 0; mt < 4; mt++)
#pragma unroll
                for (int p = 0; p < 2; p++) {
                    mma_tf32(acc[mt][2 * p],     af[mt], &bf[p][0]);
                    mma_tf32(acc[mt][2 * p + 1], af[mt], &bf[p][2]);
                }
        }
        __syncthreads();
        buf ^= 1;
    }

    const int erow = lane >> 2;
    const int ecol = (lane & 3) * 2;
#pragma unroll
    for (int mt = 0; mt < 4; mt++) {
#pragma unroll
        for (int nt = 0; nt < 4; nt++) {
            int gr = m0 + wm + mt * 16 + erow;
            int gc = n0 + wn + nt * 8 + ecol;
            float b0 = 0.f, b1 = 0.f;
            if (bias) { b0 = bias[gc]; b1 = bias[gc + 1]; }
            *(float2*)(Cm + (size_t)gr * Nc + gc) =
                make_float2(acc[mt][nt][0] + b0, acc[mt][nt][1] + b1);
            *(float2*)(Cm + (size_t)(gr + 8) * Nc + gc) =
                make_float2(acc[mt][nt][2] + b0, acc[mt][nt][3] + b1);
        }
    }
}

// ---------------------------------------------------------------------------
// Flash attention, tf32 single-pass, P via quad shuffles (no smem round-trip).
// 128 q-rows, 256 threads, 8 warps. K/Vt fp32 (pre-rounded) double-buffered.
// One __syncthreads per iteration. smem: Q + 2 x (K|Vt) = 104448 B.
// ---------------------------------------------------------------------------
#define QPAD 68
#define A_QREG (128 * QPAD * 4)       // 34816 B (Q)
#define A_KARR (64 * QPAD * 4)        // 17408 B
#define A_KSTAGE (2 * A_KARR)         // 34816 B
#define A_KBASE A_QREG

__global__ __launch_bounds__(256, 1) void attn_tf32(void) {
    extern __shared__ __align__(16) char sm[];
    const uint32_t sbase = smem_u32(sm);

    const int t = threadIdx.x;
    const int wid = t >> 5;
    const int lane = t & 31;
    const int h = blockIdx.y;
    const int b = blockIdx.z;
    const int bh = b * HH + h;
    const int q0 = blockIdx.x * 128;

    const size_t hbase = (size_t)bh * NN * 64;
    const size_t vtbase = (size_t)bh * DD * NN;

    const int srow = t >> 2, sseg = (t & 3) * 16;
    const uint32_t kdst = sbase + A_KBASE + (srow * QPAD + sseg) * 4;
    const uint32_t vdst = kdst + A_KARR;
    const float* ksrc0 = g_K + hbase + (size_t)srow * 64 + sseg;
    const float* vsrc0 = g_Vt + vtbase + (size_t)srow * NN + sseg;

#pragma unroll
    for (int c = 0; c < 4; c++) {
        cp16(kdst + c * 16, ksrc0 + c * 4);
        cp16(vdst + c * 16, vsrc0 + c * 4);
    }
    cp_commit();

    {   // stage Q
        int row = t >> 1, half = (t & 1) * 32;
        const float* src = g_Q + hbase + (size_t)(q0 + row) * 64 + half;
        float* dst = (float*)sm + row * QPAD + half;
#pragma unroll
        for (int j = 0; j < 32; j += 4)
            *(float4*)(dst + j) = *(const float4*)(src + j);
    }
    __syncthreads();

    const uint32_t arow = wid * 16 + (lane & 15);
    const uint32_t acoff = (lane >> 4) * 4;
    uint32_t qf[8][4];
#pragma unroll
    for (int ks = 0; ks < 8; ks++)
        ldmx4(qf[ks], sbase + (arow * QPAD + ks * 8 + acoff) * 4);

    float o[8][4];
#pragma unroll
    for (int i = 0; i < 8; i++)
#pragma unroll
        for (int f = 0; f < 4; f++) o[i][f] = 0.f;
    float m0 = -1e30f, m1 = -1e30f, l0 = 0.f, l1 = 0.f;

    const uint32_t b_row = ((lane >> 4) << 3) + (lane & 7);
    const uint32_t b_coff = ((lane >> 3) & 1) * 4;
    const int l4 = lane & 3;
    const int srcA = (lane & ~3) | (l4 >> 1);     // key l4 source lane
    const int srcB = srcA + 2;                    // key l4+4 source lane
    const bool oddk = (l4 & 1);

    int buf = 0;
    for (int kt = 0; kt < NN / 64; kt++) {
        if (kt + 1 < NN / 64) {
            uint32_t d = (buf ^ 1) * A_KSTAGE;
            const float* ks_ = ksrc0 + (size_t)(kt + 1) * 64 * 64;
            const float* vs_ = vsrc0 + (kt + 1) * 64;
#pragma unroll
            for (int c = 0; c < 4; c++) {
                cp16(kdst + d + c * 16, ks_ + c * 4);
                cp16(vdst + d + c * 16, vs_ + c * 4);
            }
        }
        cp_commit();
        cp_wait1();
        __syncthreads();

        const uint32_t sK = sbase + A_KBASE + buf * A_KSTAGE;
        const uint32_t sVt = sK + A_KARR;

        // ---- S = Q.K^T (log2 domain), tf32 ----
        float s[8][4];
#pragma unroll
        for (int i = 0; i < 8; i++)
#pragma unroll
            for (int f = 0; f < 4; f++) s[i][f] = 0.f;
#pragma unroll
        for (int ks = 0; ks < 8; ks++) {
            const uint32_t kc = ks * 8;
#pragma unroll
            for (int g = 0; g < 4; g++) {
                uint32_t bf[4];
                ldmx4(bf, sK + ((g * 16 + b_row) * QPAD + kc + b_coff) * 4);
                mma_tf32(s[2 * g],     qf[ks], &bf[0]);
                mma_tf32(s[2 * g + 1], qf[ks], &bf[2]);
            }
        }

        // ---- online softmax (exp2 domain; l lane-partial) ----
        float tm0 = -1e30f, tm1 = -1e30f;
#pragma unroll
        for (int nt = 0; nt < 8; nt++) {
            tm0 = fmaxf(tm0, fmaxf(s[nt][0], s[nt][1]));
            tm1 = fmaxf(tm1, fmaxf(s[nt][2], s[nt][3]));
        }
        tm0 = fmaxf(tm0, __shfl_xor_sync(0xffffffffu, tm0, 1));
        tm0 = fmaxf(tm0, __shfl_xor_sync(0xffffffffu, tm0, 2));
        tm1 = fmaxf(tm1, __shfl_xor_sync(0xffffffffu, tm1, 1));
        tm1 = fmaxf(tm1, __shfl_xor_sync(0xffffffffu, tm1, 2));
        float mn0 = fmaxf(m0, tm0), mn1 = fmaxf(m1, tm1);
        float al0 = exp2f(m0 - mn0), al1 = exp2f(m1 - mn1);
        m0 = mn0; m1 = mn1;
        float rs0 = 0.f, rs1 = 0.f;
#pragma unroll
        for (int nt = 0; nt < 8; nt++) {
            s[nt][0] = exp2f(s[nt][0] - m0);
            s[nt][1] = exp2f(s[nt][1] - m0);
            s[nt][2] = exp2f(s[nt][2] - m1);
            s[nt][3] = exp2f(s[nt][3] - m1);
            rs0 += s[nt][0] + s[nt][1];
            rs1 += s[nt][2] + s[nt][3];
        }
        l0 = l0 * al0 + rs0;
        l1 = l1 * al1 + rs1;
#pragma unroll
        for (int nt = 0; nt < 8; nt++) {
            o[nt][0] *= al0; o[nt][1] *= al0;
            o[nt][2] *= al1; o[nt][3] *= al1;
        }

        // ---- O += P.V : A-fragment built from S regs via quad shuffles ----
#pragma unroll
        for (int ks = 0; ks < 8; ks++) {
            // accumulator cols {2c,2c+1} -> A-fragment cols {c, c+4}
            float v0 = __shfl_sync(0xffffffffu, s[ks][0], srcA);
            float v1 = __shfl_sync(0xffffffffu, s[ks][1], srcA);
            float v2 = __shfl_sync(0xffffffffu, s[ks][2], srcA);
            float v3 = __shfl_sync(0xffffffffu, s[ks][3], srcA);
            float w0 = __shfl_sync(0xffffffffu, s[ks][0], srcB);
            float w1 = __shfl_sync(0xffffffffu, s[ks][1], srcB);
            float w2 = __shfl_sync(0xffffffffu, s[ks][2], srcB);
            float w3 = __shfl_sync(0xffffffffu, s[ks][3], srcB);
            uint32_t pf[4];
            pf[0] = cvt1u(oddk ? v1 : v0);   // (r,   key l4)
            pf[1] = cvt1u(oddk ? v3 : v2);   // (r+8, key l4)
            pf[2] = cvt1u(oddk ? w1 : w0);   // (r,   key l4+4)
            pf[3] = cvt1u(oddk ? w3 : w2);   // (r+8, key l4+4)

            const uint32_t kc = ks * 8;
#pragma unroll
            for (int g = 0; g < 4; g++) {
                uint32_t vf[4];
                ldmx4(vf, sVt + ((g * 16 + b_row) * QPAD + kc + b_coff) * 4);
                mma_tf32(o[2 * g],     pf, &vf[0]);
                mma_tf32(o[2 * g + 1], pf, &vf[2]);
            }
        }
        buf ^= 1;
    }

    // ---- epilogue: reduce l, write fp32 g_attn ----
    l0 += __shfl_xor_sync(0xffffffffu, l0, 1);
    l0 += __shfl_xor_sync(0xffffffffu, l0, 2);
    l1 += __shfl_xor_sync(0xffffffffu, l1, 1);
    l1 += __shfl_xor_sync(0xffffffffu, l1, 2);
    float inv0 = 1.f / l0, inv1 = 1.f / l1;
    int r0 = q0 + wid * 16 + (lane >> 2);
    int cbase = (lane & 3) * 2;
    float* op0 = g_attn + (size_t)(b * NN + r0) * CC + h * DD + cbase;
    float* op1 = op0 + (size_t)8 * CC;
#pragma unroll
    for (int nt = 0; nt < 8; nt++) {
        *(float2*)(op0 + nt * 8) = make_float2(o[nt][0] * inv0, o[nt][1] * inv0);
        *(float2*)(op1 + nt * 8) = make_float2(o[nt][2] * inv1, o[nt][3] * inv1);
    }
}

// ---------------------------------------------------------------------------
extern "C" void kernel_launch(void* const* d_in, const int* in_sizes, int n_in,
                              void* d_out, int out_size) {
    const float* x      = (const float*)d_in[0];
    const float* freqs  = (const float*)d_in[1];
    const float* w_qkv  = (const float*)d_in[2];
    const float* w_proj = (const float*)d_in[3];
    const float* b_proj = (const float*)d_in[4];
    float* out = (float*)d_out;

    float *qkv, *attn;
    cudaGetSymbolAddress((void**)&qkv, g_qkv);
    cudaGetSymbolAddress((void**)&attn, g_attn);

    static int init_done = 0;
    if (!init_done) {
        cudaFuncSetAttribute(gemm_tf32, cudaFuncAttributeMaxDynamicSharedMemorySize,
                             2 * GF_STAGE);
        cudaFuncSetAttribute(attn_tf32, cudaFuncAttributeMaxDynamicSharedMemorySize,
                             A_QREG + 2 * A_KSTAGE);
        init_done = 1;
    }

    // 1) qkv = x @ w_qkv^T   (tf32 single-pass)
    gemm_tf32<<<dim3(3 * CC / 128, MR / 128), 256, 2 * GF_STAGE>>>(
        x, w_qkv, nullptr, qkv, MR, 3 * CC, CC);
    // 2) RoPE + tf32-round Q/K; transpose + round V
    prep_qkv<<<(BB * NN * HH * 2) / 256, 256>>>(qkv, freqs);
    prep_vt<<<dim3(NN / 32, DD / 32, BB * HH), 256>>>(qkv);
    // 3) attention, tf32 single-pass, shuffle-P
    attn_tf32<<<dim3(NN / 128, HH, BB), 256, A_QREG + 2 * A_KSTAGE>>>();
    // 4) out = attn @ w_proj^T + b_proj   (tf32 single-pass)
    gemm_tf32<<<dim3(CC / 128, MR / 128), 256, 2 * GF_STAGE>>>(
        attn, w_proj, b_proj, out, MR, CC, CC);
}